// round 1
// baseline (speedup 1.0000x reference)
#include <cuda_runtime.h>
#include <math.h>

// ---- fixed problem shape (B=1) ----
#define T_      3
#define RES_    24
#define HW_     576          // RES*RES
#define THW_    1728         // T*HW
#define DIM_    768
#define HEADS_  16
#define DH_     48
#define EMB_    1024
#define MLP_    3072
#define FUSEDN_ 5376         // 3*DIM + MLP
#define KOFF_   768
#define VOFF_   1536
#define MLPOFF_ 2304
#define NBR_    75           // 3*5*5

// ---- scratch (static device globals: no allocations allowed) ----
__device__ __align__(16) float g_mod[T_ * 2 * DIM_];          // scale|shift per t
__device__ __align__(16) float g_h[THW_ * DIM_];              // modulated LN(x)
__device__ __align__(16) float g_fused[THW_ * FUSEDN_];       // q|k|v|mlp_h
__device__ __align__(16) float g_xa[THW_ * DIM_];             // attn out
__device__ __align__(16) float g_y[THW_ * DIM_];              // pre-transpose out

// ---------------------------------------------------------------------------
// Kernel A: mod[t] = silu(emb[t]) @ w_mod + b_mod      (3 x 1024 x 1536)
// ---------------------------------------------------------------------------
__global__ void k_mod(const float* __restrict__ emb,
                      const float* __restrict__ w_mod,
                      const float* __restrict__ b_mod) {
    int t   = blockIdx.y;
    int col = blockIdx.x * 256 + threadIdx.x;
    __shared__ float se[EMB_];
    for (int k = threadIdx.x; k < EMB_; k += 256) {
        float e = emb[t * EMB_ + k];
        se[k] = e / (1.f + expf(-e));
    }
    __syncthreads();
    float acc = 0.f;
    #pragma unroll 8
    for (int k = 0; k < EMB_; k++)
        acc += se[k] * w_mod[k * (2 * DIM_) + col];
    g_mod[t * (2 * DIM_) + col] = acc + b_mod[col];
}

// ---------------------------------------------------------------------------
// Kernel B: per-token LN of x (transposed) + modulate -> g_h
// ---------------------------------------------------------------------------
__global__ void k_lnmod(const float* __restrict__ x) {
    int p  = blockIdx.x;
    int t  = p / HW_;
    int hw = p % HW_;
    const float* xp = x + (size_t)t * DIM_ * HW_ + hw;   // stride HW_ over d
    int tid = threadIdx.x;

    float v[3];
    float sum = 0.f, sq = 0.f;
    #pragma unroll
    for (int i = 0; i < 3; i++) {
        v[i] = xp[(size_t)(tid + i * 256) * HW_];
        sum += v[i];
        sq  += v[i] * v[i];
    }
    __shared__ float s1[256], s2[256];
    s1[tid] = sum; s2[tid] = sq;
    __syncthreads();
    for (int o = 128; o; o >>= 1) {
        if (tid < o) { s1[tid] += s1[tid + o]; s2[tid] += s2[tid + o]; }
        __syncthreads();
    }
    float mean = s1[0] * (1.f / 768.f);
    float var  = s2[0] * (1.f / 768.f) - mean * mean;
    float rinv = rsqrtf(var + 1e-5f);
    #pragma unroll
    for (int i = 0; i < 3; i++) {
        int d = tid + i * 256;
        float sc = g_mod[t * 1536 + d];
        float sh = g_mod[t * 1536 + 768 + d];
        g_h[(size_t)p * DIM_ + d] = (v[i] - mean) * rinv * (1.f + sc) + sh;
    }
}

// ---------------------------------------------------------------------------
// Kernel C: fused = g_h @ W_fused + b_fused      (1728 x 5376, K=768)
// classic 64x64x16 SGEMM, 256 threads, 4x4 per thread
// ---------------------------------------------------------------------------
__global__ void k_gemm_fused(const float* __restrict__ B,
                             const float* __restrict__ bias) {
    __shared__ __align__(16) float As[16][64];
    __shared__ __align__(16) float Bs[16][64];
    int tid = threadIdx.x;
    int tx = tid & 15, ty = tid >> 4;
    int m0 = blockIdx.y * 64, n0 = blockIdx.x * 64;
    int am = tid >> 2, ak = (tid & 3) * 4;
    int bk = tid >> 4, bn = (tid & 15) * 4;

    float acc[4][4] = {};
    for (int k0 = 0; k0 < DIM_; k0 += 16) {
        float4 a4 = *(const float4*)(g_h + (size_t)(m0 + am) * DIM_ + k0 + ak);
        float4 b4 = *(const float4*)(B + (size_t)(k0 + bk) * FUSEDN_ + n0 + bn);
        As[ak + 0][am] = a4.x; As[ak + 1][am] = a4.y;
        As[ak + 2][am] = a4.z; As[ak + 3][am] = a4.w;
        *(float4*)&Bs[bk][bn] = b4;
        __syncthreads();
        #pragma unroll
        for (int k = 0; k < 16; k++) {
            float4 a = *(const float4*)&As[k][ty * 4];
            float4 b = *(const float4*)&Bs[k][tx * 4];
            acc[0][0] += a.x * b.x; acc[0][1] += a.x * b.y; acc[0][2] += a.x * b.z; acc[0][3] += a.x * b.w;
            acc[1][0] += a.y * b.x; acc[1][1] += a.y * b.y; acc[1][2] += a.y * b.z; acc[1][3] += a.y * b.w;
            acc[2][0] += a.z * b.x; acc[2][1] += a.z * b.y; acc[2][2] += a.z * b.z; acc[2][3] += a.z * b.w;
            acc[3][0] += a.w * b.x; acc[3][1] += a.w * b.y; acc[3][2] += a.w * b.z; acc[3][3] += a.w * b.w;
        }
        __syncthreads();
    }
    #pragma unroll
    for (int i = 0; i < 4; i++) {
        int m = m0 + ty * 4 + i;
        #pragma unroll
        for (int j = 0; j < 4; j++) {
            int n = n0 + tx * 4 + j;
            g_fused[(size_t)m * FUSEDN_ + n] = acc[i][j] + bias[n];
        }
    }
}

// ---------------------------------------------------------------------------
// Kernel D: per-(token, head) LayerNorm(q/k) + 3D RoPE + q scale. In place.
// one warp per (p, head); lanes 0..23 own rope pairs.
// ---------------------------------------------------------------------------
__global__ void k_qk(const float* __restrict__ qn_w, const float* __restrict__ qn_b,
                     const float* __restrict__ kn_w, const float* __restrict__ kn_b) {
    int gw = (blockIdx.x * blockDim.x + threadIdx.x) >> 5;
    int lane = threadIdx.x & 31;
    if (gw >= THW_ * HEADS_) return;
    int p = gw / HEADS_;
    int head = gw % HEADS_;
    int t = p / HW_, hw = p % HW_;
    int hh = hw / RES_, ww = hw % RES_;

    float coord = (lane < 8) ? (float)t : (lane < 16) ? (float)hh : (float)ww;
    float inv = powf(10000.f, -(float)(lane & 7) * 0.125f);
    float ang = coord * inv;
    float c = cosf(ang), s = sinf(ang);

    #pragma unroll
    for (int which = 0; which < 2; which++) {
        float* base = g_fused + (size_t)p * FUSEDN_ + which * 768 + head * DH_;
        float x1 = 0.f, x2 = 0.f;
        if (lane < 24) { x1 = base[2 * lane]; x2 = base[2 * lane + 1]; }
        float sum = x1 + x2;
        float sq  = x1 * x1 + x2 * x2;
        #pragma unroll
        for (int o = 16; o; o >>= 1) {
            sum += __shfl_xor_sync(0xffffffffu, sum, o);
            sq  += __shfl_xor_sync(0xffffffffu, sq, o);
        }
        float mean = sum * (1.f / 48.f);
        float var  = sq * (1.f / 48.f) - mean * mean;
        float rinv = rsqrtf(var + 1e-5f);
        if (lane < 24) {
            const float* w = which ? kn_w : qn_w;
            const float* b = which ? kn_b : qn_b;
            float y1 = (x1 - mean) * rinv * w[2 * lane]     + b[2 * lane];
            float y2 = (x2 - mean) * rinv * w[2 * lane + 1] + b[2 * lane + 1];
            float o1 = y1 * c - y2 * s;
            float o2 = y1 * s + y2 * c;
            if (which == 0) { o1 *= 0.14433756729740643f; o2 *= 0.14433756729740643f; }
            base[2 * lane]     = o1;
            base[2 * lane + 1] = o2;
        }
    }
}

// ---------------------------------------------------------------------------
// Kernel E: neighborhood attention. one warp per (p, head); 75 neighbors.
// ---------------------------------------------------------------------------
__global__ void k_attn() {
    int warp = threadIdx.x >> 5;
    int lane = threadIdx.x & 31;
    int gw = blockIdx.x * 8 + warp;
    if (gw >= THW_ * HEADS_) return;
    int head = gw % HEADS_;
    int p = gw / HEADS_;
    int t = p / HW_, hw = p % HW_;
    int h = hw / RES_, w = hw % RES_;
    (void)t;

    __shared__ float ssc[8][80];
    __shared__ int   spk[8][80];
    float* sc = ssc[warp];
    int*   pk = spk[warp];

    int h0 = min(max(h - 2, 0), RES_ - 5);
    int w0 = min(max(w - 2, 0), RES_ - 5);
    for (int j = lane; j < NBR_; j += 32) {
        int a = j / 25, r = j % 25, cc = r / 5, e = r % 5;
        pk[j] = (a * RES_ + h0 + cc) * RES_ + (w0 + e);  // ta = a (T window = all 3)
    }
    __syncwarp();

    const float* qp = g_fused + (size_t)p * FUSEDN_ + head * DH_;
    float qa = qp[lane];
    float qb = (lane < 16) ? qp[32 + lane] : 0.f;

    for (int j = 0; j < NBR_; j++) {
        const float* kp = g_fused + (size_t)pk[j] * FUSEDN_ + KOFF_ + head * DH_;
        float partial = qa * kp[lane];
        if (lane < 16) partial += qb * kp[32 + lane];
        #pragma unroll
        for (int o = 16; o; o >>= 1)
            partial += __shfl_xor_sync(0xffffffffu, partial, o);
        if (lane == 0) sc[j] = partial;
    }
    __syncwarp();

    // softmax over 75
    float m = -1e30f;
    for (int j = lane; j < NBR_; j += 32) m = fmaxf(m, sc[j]);
    #pragma unroll
    for (int o = 16; o; o >>= 1) m = fmaxf(m, __shfl_xor_sync(0xffffffffu, m, o));
    float sum = 0.f;
    for (int j = lane; j < NBR_; j += 32) {
        float e = __expf(sc[j] - m);
        sc[j] = e;
        sum += e;
    }
    #pragma unroll
    for (int o = 16; o; o >>= 1) sum += __shfl_xor_sync(0xffffffffu, sum, o);
    float rs = 1.f / sum;
    for (int j = lane; j < NBR_; j += 32) sc[j] *= rs;
    __syncwarp();

    float acc_a = 0.f, acc_b = 0.f;
    for (int j = 0; j < NBR_; j++) {
        const float* vp = g_fused + (size_t)pk[j] * FUSEDN_ + VOFF_ + head * DH_;
        float pj = sc[j];
        acc_a += pj * vp[lane];
        if (lane < 16) acc_b += pj * vp[32 + lane];
    }
    g_xa[(size_t)p * DIM_ + head * DH_ + lane] = acc_a;
    if (lane < 16)
        g_xa[(size_t)p * DIM_ + head * DH_ + 32 + lane] = acc_b;
}

// ---------------------------------------------------------------------------
// Kernel F0: in-place silu on mlp_h region of g_fused
// ---------------------------------------------------------------------------
__global__ void k_silu() {
    int i = blockIdx.x * 256 + threadIdx.x;
    if (i < THW_ * MLP_) {
        int p = i / MLP_, c = i % MLP_;
        size_t idx = (size_t)p * FUSEDN_ + MLPOFF_ + c;
        float v = g_fused[idx];
        g_fused[idx] = v / (1.f + expf(-v));
    }
}

// ---------------------------------------------------------------------------
// Kernel F: y = skip + xa@W_out + silu(mlp)@W_mlp + b_mlp
// one GEMM with K = 768 (+) 3072, two A/B sources. Writes g_y [p][d].
// ---------------------------------------------------------------------------
__global__ void k_gemm_final(const float* __restrict__ Wout,
                             const float* __restrict__ Wmlp,
                             const float* __restrict__ bmlp,
                             const float* __restrict__ x) {
    __shared__ __align__(16) float As[16][64];
    __shared__ __align__(16) float Bs[16][64];
    int tid = threadIdx.x;
    int tx = tid & 15, ty = tid >> 4;
    int m0 = blockIdx.y * 64, n0 = blockIdx.x * 64;
    int am = tid >> 2, ak = (tid & 3) * 4;
    int bk = tid >> 4, bn = (tid & 15) * 4;

    float acc[4][4] = {};
    for (int k0 = 0; k0 < 3840; k0 += 16) {
        float4 a4, b4;
        if (k0 < 768) {
            a4 = *(const float4*)(g_xa + (size_t)(m0 + am) * DIM_ + k0 + ak);
            b4 = *(const float4*)(Wout + (size_t)(k0 + bk) * DIM_ + n0 + bn);
        } else {
            int kk = k0 - 768;
            a4 = *(const float4*)(g_fused + (size_t)(m0 + am) * FUSEDN_ + MLPOFF_ + kk + ak);
            b4 = *(const float4*)(Wmlp + (size_t)(kk + bk) * DIM_ + n0 + bn);
        }
        As[ak + 0][am] = a4.x; As[ak + 1][am] = a4.y;
        As[ak + 2][am] = a4.z; As[ak + 3][am] = a4.w;
        *(float4*)&Bs[bk][bn] = b4;
        __syncthreads();
        #pragma unroll
        for (int k = 0; k < 16; k++) {
            float4 a = *(const float4*)&As[k][ty * 4];
            float4 b = *(const float4*)&Bs[k][tx * 4];
            acc[0][0] += a.x * b.x; acc[0][1] += a.x * b.y; acc[0][2] += a.x * b.z; acc[0][3] += a.x * b.w;
            acc[1][0] += a.y * b.x; acc[1][1] += a.y * b.y; acc[1][2] += a.y * b.z; acc[1][3] += a.y * b.w;
            acc[2][0] += a.z * b.x; acc[2][1] += a.z * b.y; acc[2][2] += a.z * b.z; acc[2][3] += a.z * b.w;
            acc[3][0] += a.w * b.x; acc[3][1] += a.w * b.y; acc[3][2] += a.w * b.z; acc[3][3] += a.w * b.w;
        }
        __syncthreads();
    }
    #pragma unroll
    for (int i = 0; i < 4; i++) {
        int m = m0 + ty * 4 + i;
        int t = m / HW_, hw = m % HW_;
        #pragma unroll
        for (int j = 0; j < 4; j++) {
            int n = n0 + tx * 4 + j;
            float skip = x[((size_t)t * DIM_ + n) * HW_ + hw];
            g_y[(size_t)m * DIM_ + n] = acc[i][j] + bmlp[n] + skip;
        }
    }
}

// ---------------------------------------------------------------------------
// Kernel G: transpose g_y [t*576+hw][d] -> out [t][d][hw]
// ---------------------------------------------------------------------------
__global__ void k_out(float* __restrict__ out) {
    __shared__ float tile[32][33];
    int t = blockIdx.z;
    int hw0 = blockIdx.x * 32, d0 = blockIdx.y * 32;
    int tx = threadIdx.x, ty = threadIdx.y;
    #pragma unroll
    for (int i = 0; i < 4; i++) {
        int hw = hw0 + ty + i * 8;
        tile[ty + i * 8][tx] = g_y[((size_t)t * HW_ + hw) * DIM_ + d0 + tx];
    }
    __syncthreads();
    #pragma unroll
    for (int i = 0; i < 4; i++) {
        int d = d0 + ty + i * 8;
        out[((size_t)t * DIM_ + d) * HW_ + hw0 + tx] = tile[tx][ty + i * 8];
    }
}

// ---------------------------------------------------------------------------
extern "C" void kernel_launch(void* const* d_in, const int* in_sizes, int n_in,
                              void* d_out, int out_size) {
    const float* x       = (const float*)d_in[0];
    const float* emb     = (const float*)d_in[1];
    const float* w_mod   = (const float*)d_in[2];
    const float* b_mod   = (const float*)d_in[3];
    const float* qn_w    = (const float*)d_in[4];
    const float* qn_b    = (const float*)d_in[5];
    const float* kn_w    = (const float*)d_in[6];
    const float* kn_b    = (const float*)d_in[7];
    const float* W_fused = (const float*)d_in[8];
    const float* b_fused = (const float*)d_in[9];
    const float* W_out   = (const float*)d_in[10];
    const float* W_mlp   = (const float*)d_in[11];
    const float* b_mlp   = (const float*)d_in[12];
    float* out = (float*)d_out;

    k_mod<<<dim3(6, 3), 256>>>(emb, w_mod, b_mod);
    k_lnmod<<<THW_, 256>>>(x);
    k_gemm_fused<<<dim3(FUSEDN_ / 64, THW_ / 64), 256>>>(W_fused, b_fused);
    k_qk<<<(THW_ * HEADS_) / 8, 256>>>(qn_w, qn_b, kn_w, kn_b);
    k_attn<<<(THW_ * HEADS_) / 8, 256>>>();
    k_silu<<<(THW_ * MLP_ + 255) / 256, 256>>>();
    k_gemm_final<<<dim3(DIM_ / 64, THW_ / 64), 256>>>(W_out, W_mlp, b_mlp, x);
    k_out<<<dim3(HW_ / 32, DIM_ / 32, T_), dim3(32, 8)>>>(out);
}

// round 4
// speedup vs baseline: 1.7934x; 1.7934x over previous
#include <cuda_runtime.h>
#include <math.h>
#include <stdint.h>

// ---- fixed problem shape (B=1) ----
#define T_      3
#define RES_    24
#define HW_     576
#define THW_    1728
#define DIM_    768
#define HEADS_  16
#define DH_     48
#define EMB_    1024
#define MLP_    3072
#define FUSEDN_ 5376
#define KOFF_   768
#define VOFF_   1536
#define MLPOFF_ 2304
#define NBR_    75
#define KFIN_   3840         // 768 + 3072

// ---- scratch ----
__device__ __align__(16) float g_mod[T_ * 2 * DIM_];
__device__ __align__(16) float g_h[THW_ * DIM_];
__device__ __align__(16) float g_fused[THW_ * FUSEDN_];
__device__ __align__(16) float g_afin[THW_ * KFIN_];       // [xa | silu(mlp_h)]
__device__ __align__(16) float g_y[THW_ * DIM_];
__device__ __align__(16) float g_WtF[FUSEDN_ * DIM_];      // W_fused^T [5376][768]
__device__ __align__(16) float g_WtFin[DIM_ * KFIN_];      // [768][3840] = [Wout^T|Wmlp^T]

__device__ __forceinline__ uint32_t f2tf32(float f) {
    uint32_t u;
    asm("cvt.rna.tf32.f32 %0, %1;" : "=r"(u) : "f"(f));
    return u;
}

__device__ __forceinline__ void mma_tf32(float* c, const uint32_t* a, const uint32_t* b) {
    asm volatile(
        "mma.sync.aligned.m16n8k8.row.col.f32.tf32.tf32.f32 "
        "{%0,%1,%2,%3}, {%4,%5,%6,%7}, {%8,%9}, {%0,%1,%2,%3};"
        : "+f"(c[0]), "+f"(c[1]), "+f"(c[2]), "+f"(c[3])
        : "r"(a[0]), "r"(a[1]), "r"(a[2]), "r"(a[3]), "r"(b[0]), "r"(b[1]));
}

// ===================== tensor-core GEMM (mma.sync tf32) =====================
// C[m][n] = sum_k A[m][k]*Bt[n][k] + bias[n] (+skip). Tile 128x128, K-chunk 32.
// 256 threads: warps 2(m) x 4(n); warp tile 64x32.
__global__ void __launch_bounds__(256) k_gemm_tc(
        const float* __restrict__ A, int lda,
        const float* __restrict__ Bt, int Ktot,
        const float* __restrict__ bias,
        float* __restrict__ C, int ldc,
        const float* __restrict__ xskip) {
    __shared__ __align__(16) float As[128][36];
    __shared__ __align__(16) float Bs[128][36];

    int tid = threadIdx.x;
    int wid = tid >> 5, lane = tid & 31;
    int wm = wid >> 2, wn = wid & 3;            // warp coords
    int lr = lane >> 2, lc = lane & 3;
    int m0 = blockIdx.y * 128, n0 = blockIdx.x * 128;

    float acc[4][4][4];
    #pragma unroll
    for (int i = 0; i < 4; i++)
        #pragma unroll
        for (int j = 0; j < 4; j++)
            #pragma unroll
            for (int r = 0; r < 4; r++) acc[i][j][r] = 0.f;

    for (int k0 = 0; k0 < Ktot; k0 += 32) {
        __syncthreads();
        // cooperative load 128x32 of A and Bt, converting to tf32 bits
        #pragma unroll
        for (int it = 0; it < 4; it++) {
            int idx = it * 256 + tid;
            int row = idx >> 3, c4 = (idx & 7) * 4;
            int m = m0 + row;
            float4 va = make_float4(0.f, 0.f, 0.f, 0.f);
            if (m < THW_) va = *(const float4*)(A + (size_t)m * lda + k0 + c4);
            As[row][c4 + 0] = __uint_as_float(f2tf32(va.x));
            As[row][c4 + 1] = __uint_as_float(f2tf32(va.y));
            As[row][c4 + 2] = __uint_as_float(f2tf32(va.z));
            As[row][c4 + 3] = __uint_as_float(f2tf32(va.w));
            float4 vb = *(const float4*)(Bt + (size_t)(n0 + row) * Ktot + k0 + c4);
            Bs[row][c4 + 0] = __uint_as_float(f2tf32(vb.x));
            Bs[row][c4 + 1] = __uint_as_float(f2tf32(vb.y));
            Bs[row][c4 + 2] = __uint_as_float(f2tf32(vb.z));
            Bs[row][c4 + 3] = __uint_as_float(f2tf32(vb.w));
        }
        __syncthreads();

        #pragma unroll
        for (int ks = 0; ks < 4; ks++) {
            int kb = ks * 8;
            uint32_t af[4][4], bf[4][2];
            #pragma unroll
            for (int mt = 0; mt < 4; mt++) {
                int r = wm * 64 + mt * 16 + lr;
                af[mt][0] = __float_as_uint(As[r][kb + lc]);
                af[mt][1] = __float_as_uint(As[r + 8][kb + lc]);
                af[mt][2] = __float_as_uint(As[r][kb + lc + 4]);
                af[mt][3] = __float_as_uint(As[r + 8][kb + lc + 4]);
            }
            #pragma unroll
            for (int nt = 0; nt < 4; nt++) {
                int r = wn * 32 + nt * 8 + lr;
                bf[nt][0] = __float_as_uint(Bs[r][kb + lc]);
                bf[nt][1] = __float_as_uint(Bs[r][kb + lc + 4]);
            }
            #pragma unroll
            for (int mt = 0; mt < 4; mt++)
                #pragma unroll
                for (int nt = 0; nt < 4; nt++)
                    mma_tf32(acc[mt][nt], af[mt], bf[nt]);
        }
    }

    // epilogue: c0=(r, c), c1=(r, c+1), c2=(r+8, c), c3=(r+8, c+1)
    #pragma unroll
    for (int mt = 0; mt < 4; mt++) {
        #pragma unroll
        for (int half = 0; half < 2; half++) {
            int mrow = m0 + wm * 64 + mt * 16 + lr + half * 8;
            if (mrow >= THW_) continue;
            int t = mrow / HW_, hw = mrow % HW_;
            #pragma unroll
            for (int nt = 0; nt < 4; nt++) {
                int n = n0 + wn * 32 + nt * 8 + 2 * lc;
                float v0 = acc[mt][nt][half * 2 + 0] + bias[n];
                float v1 = acc[mt][nt][half * 2 + 1] + bias[n + 1];
                if (xskip) {
                    v0 += xskip[((size_t)t * DIM_ + n) * HW_ + hw];
                    v1 += xskip[((size_t)t * DIM_ + n + 1) * HW_ + hw];
                }
                *(float2*)(C + (size_t)mrow * ldc + n) = make_float2(v0, v1);
            }
        }
    }
}

// ===================== weight transposes =====================
__global__ void k_twf(const float* __restrict__ W) {   // [768][5376] -> [5376][768]
    __shared__ float tile[32][33];
    int nb = blockIdx.x * 32, kb = blockIdx.y * 32;
    int tx = threadIdx.x, ty = threadIdx.y;
    #pragma unroll
    for (int i = 0; i < 4; i++)
        tile[ty + i * 8][tx] = W[(size_t)(kb + ty + i * 8) * FUSEDN_ + nb + tx];
    __syncthreads();
    #pragma unroll
    for (int i = 0; i < 4; i++)
        g_WtF[(size_t)(nb + ty + i * 8) * DIM_ + kb + tx] = tile[tx][ty + i * 8];
}
__global__ void k_twfin(const float* __restrict__ Wout, const float* __restrict__ Wmlp) {
    __shared__ float tile[32][33];
    int nb = blockIdx.x * 32, kb = blockIdx.y * 32;
    int tx = threadIdx.x, ty = threadIdx.y;
    #pragma unroll
    for (int i = 0; i < 4; i++) {
        int kk = kb + ty + i * 8, n = nb + tx;
        tile[ty + i * 8][tx] = (kk < DIM_) ? Wout[(size_t)kk * DIM_ + n]
                                           : Wmlp[(size_t)(kk - DIM_) * DIM_ + n];
    }
    __syncthreads();
    #pragma unroll
    for (int i = 0; i < 4; i++)
        g_WtFin[(size_t)(nb + ty + i * 8) * KFIN_ + kb + tx] = tile[tx][ty + i * 8];
}

// ===================== elementwise / attention =====================
__global__ void k_mod(const float* __restrict__ emb, const float* __restrict__ w_mod,
                      const float* __restrict__ b_mod) {
    int t = blockIdx.y, col = blockIdx.x * 256 + threadIdx.x;
    __shared__ float se[EMB_];
    for (int k = threadIdx.x; k < EMB_; k += 256) {
        float e = emb[t * EMB_ + k];
        se[k] = e / (1.f + expf(-e));
    }
    __syncthreads();
    float acc = 0.f;
    #pragma unroll 8
    for (int k = 0; k < EMB_; k++) acc += se[k] * w_mod[k * (2 * DIM_) + col];
    g_mod[t * (2 * DIM_) + col] = acc + b_mod[col];
}

__global__ void k_lnmod(const float* __restrict__ x) {
    int p = blockIdx.x, t = p / HW_, hw = p % HW_;
    const float* xp = x + (size_t)t * DIM_ * HW_ + hw;
    int tid = threadIdx.x;
    float v[3], sum = 0.f, sq = 0.f;
    #pragma unroll
    for (int i = 0; i < 3; i++) {
        v[i] = xp[(size_t)(tid + i * 256) * HW_];
        sum += v[i]; sq += v[i] * v[i];
    }
    __shared__ float s1[256], s2[256];
    s1[tid] = sum; s2[tid] = sq;
    __syncthreads();
    for (int o = 128; o; o >>= 1) {
        if (tid < o) { s1[tid] += s1[tid + o]; s2[tid] += s2[tid + o]; }
        __syncthreads();
    }
    float mean = s1[0] * (1.f / 768.f);
    float var = s2[0] * (1.f / 768.f) - mean * mean;
    float rinv = rsqrtf(var + 1e-5f);
    #pragma unroll
    for (int i = 0; i < 3; i++) {
        int d = tid + i * 256;
        float sc = g_mod[t * 1536 + d], sh = g_mod[t * 1536 + 768 + d];
        g_h[(size_t)p * DIM_ + d] = (v[i] - mean) * rinv * (1.f + sc) + sh;
    }
}

__global__ void k_qk(const float* __restrict__ qn_w, const float* __restrict__ qn_b,
                     const float* __restrict__ kn_w, const float* __restrict__ kn_b) {
    int gw = (blockIdx.x * blockDim.x + threadIdx.x) >> 5;
    int lane = threadIdx.x & 31;
    if (gw >= THW_ * HEADS_) return;
    int p = gw / HEADS_, head = gw % HEADS_;
    int t = p / HW_, hw = p % HW_;
    int hh = hw / RES_, ww = hw % RES_;
    float coord = (lane < 8) ? (float)t : (lane < 16) ? (float)hh : (float)ww;
    float inv = powf(10000.f, -(float)(lane & 7) * 0.125f);
    float ang = coord * inv;
    float c = cosf(ang), s = sinf(ang);
    #pragma unroll
    for (int which = 0; which < 2; which++) {
        float* base = g_fused + (size_t)p * FUSEDN_ + which * 768 + head * DH_;
        float x1 = 0.f, x2 = 0.f;
        if (lane < 24) { x1 = base[2 * lane]; x2 = base[2 * lane + 1]; }
        float sum = x1 + x2, sq = x1 * x1 + x2 * x2;
        #pragma unroll
        for (int o = 16; o; o >>= 1) {
            sum += __shfl_xor_sync(0xffffffffu, sum, o);
            sq  += __shfl_xor_sync(0xffffffffu, sq, o);
        }
        float mean = sum * (1.f / 48.f);
        float var = sq * (1.f / 48.f) - mean * mean;
        float rinv = rsqrtf(var + 1e-5f);
        if (lane < 24) {
            const float* w = which ? kn_w : qn_w;
            const float* b = which ? kn_b : qn_b;
            float y1 = (x1 - mean) * rinv * w[2 * lane]     + b[2 * lane];
            float y2 = (x2 - mean) * rinv * w[2 * lane + 1] + b[2 * lane + 1];
            float o1 = y1 * c - y2 * s;
            float o2 = y1 * s + y2 * c;
            if (which == 0) { o1 *= 0.14433756729740643f; o2 *= 0.14433756729740643f; }
            base[2 * lane] = o1; base[2 * lane + 1] = o2;
        }
    }
}

__global__ void k_attn() {
    int warp = threadIdx.x >> 5, lane = threadIdx.x & 31;
    int gw = blockIdx.x * 8 + warp;
    if (gw >= THW_ * HEADS_) return;
    int head = gw % HEADS_, p = gw / HEADS_;
    int hw = p % HW_;
    int h = hw / RES_, w = hw % RES_;
    __shared__ float ssc[8][80];
    __shared__ int spk[8][80];
    float* sc = ssc[warp];
    int* pk = spk[warp];
    int h0 = min(max(h - 2, 0), RES_ - 5);
    int w0 = min(max(w - 2, 0), RES_ - 5);
    for (int j = lane; j < NBR_; j += 32) {
        int a = j / 25, r = j % 25, cc = r / 5, e = r % 5;
        pk[j] = (a * RES_ + h0 + cc) * RES_ + (w0 + e);
    }
    __syncwarp();
    const float* qp = g_fused + (size_t)p * FUSEDN_ + head * DH_;
    float qa = qp[lane];
    float qb = (lane < 16) ? qp[32 + lane] : 0.f;
    for (int j = 0; j < NBR_; j++) {
        const float* kp = g_fused + (size_t)pk[j] * FUSEDN_ + KOFF_ + head * DH_;
        float partial = qa * kp[lane];
        if (lane < 16) partial += qb * kp[32 + lane];
        #pragma unroll
        for (int o = 16; o; o >>= 1) partial += __shfl_xor_sync(0xffffffffu, partial, o);
        if (lane == 0) sc[j] = partial;
    }
    __syncwarp();
    float m = -1e30f;
    for (int j = lane; j < NBR_; j += 32) m = fmaxf(m, sc[j]);
    #pragma unroll
    for (int o = 16; o; o >>= 1) m = fmaxf(m, __shfl_xor_sync(0xffffffffu, m, o));
    float sum = 0.f;
    for (int j = lane; j < NBR_; j += 32) {
        float e = __expf(sc[j] - m);
        sc[j] = e; sum += e;
    }
    #pragma unroll
    for (int o = 16; o; o >>= 1) sum += __shfl_xor_sync(0xffffffffu, sum, o);
    float rs = 1.f / sum;
    for (int j = lane; j < NBR_; j += 32) sc[j] *= rs;
    __syncwarp();
    float acc_a = 0.f, acc_b = 0.f;
    for (int j = 0; j < NBR_; j++) {
        const float* vp = g_fused + (size_t)pk[j] * FUSEDN_ + VOFF_ + head * DH_;
        float pj = sc[j];
        acc_a += pj * vp[lane];
        if (lane < 16) acc_b += pj * vp[32 + lane];
    }
    g_afin[(size_t)p * KFIN_ + head * DH_ + lane] = acc_a;
    if (lane < 16) g_afin[(size_t)p * KFIN_ + head * DH_ + 32 + lane] = acc_b;
}

__global__ void k_silu() {
    int i = blockIdx.x * 256 + threadIdx.x;
    if (i < THW_ * MLP_) {
        int p = i / MLP_, c = i % MLP_;
        float v = g_fused[(size_t)p * FUSEDN_ + MLPOFF_ + c];
        g_afin[(size_t)p * KFIN_ + 768 + c] = v / (1.f + expf(-v));
    }
}

__global__ void k_out(float* __restrict__ out) {
    __shared__ float tile[32][33];
    int t = blockIdx.z;
    int hw0 = blockIdx.x * 32, d0 = blockIdx.y * 32;
    int tx = threadIdx.x, ty = threadIdx.y;
    #pragma unroll
    for (int i = 0; i < 4; i++)
        tile[ty + i * 8][tx] = g_y[((size_t)t * HW_ + hw0 + ty + i * 8) * DIM_ + d0 + tx];
    __syncthreads();
    #pragma unroll
    for (int i = 0; i < 4; i++)
        out[((size_t)t * DIM_ + d0 + ty + i * 8) * HW_ + hw0 + tx] = tile[tx][ty + i * 8];
}

// ===================== launch =====================
extern "C" void kernel_launch(void* const* d_in, const int* in_sizes, int n_in,
                              void* d_out, int out_size) {
    const float* x       = (const float*)d_in[0];
    const float* emb     = (const float*)d_in[1];
    const float* w_mod   = (const float*)d_in[2];
    const float* b_mod   = (const float*)d_in[3];
    const float* qn_w    = (const float*)d_in[4];
    const float* qn_b    = (const float*)d_in[5];
    const float* kn_w    = (const float*)d_in[6];
    const float* kn_b    = (const float*)d_in[7];
    const float* W_fused = (const float*)d_in[8];
    const float* b_fused = (const float*)d_in[9];
    const float* W_out   = (const float*)d_in[10];
    const float* W_mlp   = (const float*)d_in[11];
    const float* b_mlp   = (const float*)d_in[12];
    float* out = (float*)d_out;

    float* WtF;    cudaGetSymbolAddress((void**)&WtF, g_WtF);
    float* WtFin;  cudaGetSymbolAddress((void**)&WtFin, g_WtFin);
    float* gh;     cudaGetSymbolAddress((void**)&gh, g_h);
    float* gfused; cudaGetSymbolAddress((void**)&gfused, g_fused);
    float* gafin;  cudaGetSymbolAddress((void**)&gafin, g_afin);
    float* gy;     cudaGetSymbolAddress((void**)&gy, g_y);

    k_mod<<<dim3(6, 3), 256>>>(emb, w_mod, b_mod);
    k_lnmod<<<THW_, 256>>>(x);
    k_twf<<<dim3(FUSEDN_ / 32, DIM_ / 32), dim3(32, 8)>>>(W_fused);
    k_twfin<<<dim3(DIM_ / 32, KFIN_ / 32), dim3(32, 8)>>>(W_out, W_mlp);
    // fused = h @ W_fused + b_fused   (1728 x 5376, K=768)
    k_gemm_tc<<<dim3(FUSEDN_ / 128, 14), 256>>>(gh, DIM_, WtF, DIM_, b_fused,
                                                gfused, FUSEDN_, nullptr);
    k_qk<<<(THW_ * HEADS_) / 8, 256>>>(qn_w, qn_b, kn_w, kn_b);
    k_attn<<<(THW_ * HEADS_) / 8, 256>>>();
    k_silu<<<(THW_ * MLP_ + 255) / 256, 256>>>();
    // y = skip + xa@W_out + silu(mlp)@W_mlp + b_mlp   (1728 x 768, K=3840)
    k_gemm_tc<<<dim3(DIM_ / 128, 14), 256>>>(gafin, KFIN_, WtFin, KFIN_, b_mlp,
                                             gy, DIM_, x);
    k_out<<<dim3(HW_ / 32, DIM_ / 32, T_), dim3(32, 8)>>>(out);
}

// round 6
// speedup vs baseline: 1.9460x; 1.0851x over previous
#include <cuda_runtime.h>
#include <math.h>
#include <stdint.h>

// ---- fixed problem shape (B=1) ----
#define T_      3
#define RES_    24
#define HW_     576
#define THW_    1728
#define DIM_    768
#define HEADS_  16
#define DH_     48
#define EMB_    1024
#define MLP_    3072
#define FUSEDN_ 5376
#define KOFF_   768
#define VOFF_   1536
#define MLPOFF_ 2304
#define NBR_    75
#define KFIN_   3840         // 768 + 3072

// ---- scratch ----
__device__ __align__(16) float g_mod[T_ * 2 * DIM_];
__device__ __align__(16) float g_h[THW_ * DIM_];
__device__ __align__(16) float g_fused[THW_ * FUSEDN_];
__device__ __align__(16) float g_afin[THW_ * KFIN_];       // [xa | silu(mlp_h)]
__device__ __align__(16) float g_y[THW_ * DIM_];
__device__ __align__(16) float g_WtF[FUSEDN_ * DIM_];      // W_fused^T [5376][768]
__device__ __align__(16) float g_WtFin[DIM_ * KFIN_];      // [768][3840] = [Wout^T|Wmlp^T]

__device__ __forceinline__ uint32_t f2tf32(float f) {
    uint32_t u;
    asm("cvt.rna.tf32.f32 %0, %1;" : "=r"(u) : "f"(f));
    return u;
}
__device__ __forceinline__ uint32_t smem_u32(const void* p) {
    uint32_t a;
    asm("{ .reg .u64 t; cvta.to.shared.u64 t, %1; cvt.u32.u64 %0, t; }" : "=r"(a) : "l"(p));
    return a;
}
__device__ __forceinline__ void cp16(uint32_t dst, const void* src, int srcsize) {
    asm volatile("cp.async.cg.shared.global [%0], [%1], 16, %2;"
                 :: "r"(dst), "l"(src), "r"(srcsize));
}
#define CP_COMMIT() asm volatile("cp.async.commit_group;" ::: "memory")
#define CP_WAIT0()  asm volatile("cp.async.wait_group 0;" ::: "memory")
#define CP_WAIT1()  asm volatile("cp.async.wait_group 1;" ::: "memory")

__device__ __forceinline__ void mma_tf32(float* c, const uint32_t* a, const uint32_t* b) {
    asm volatile(
        "mma.sync.aligned.m16n8k8.row.col.f32.tf32.tf32.f32 "
        "{%0,%1,%2,%3}, {%4,%5,%6,%7}, {%8,%9}, {%0,%1,%2,%3};"
        : "+f"(c[0]), "+f"(c[1]), "+f"(c[2]), "+f"(c[3])
        : "r"(a[0]), "r"(a[1]), "r"(a[2]), "r"(a[3]), "r"(b[0]), "r"(b[1]));
}

// ===================== pipelined tensor-core GEMM (mma.sync tf32) =====================
// C[m][n] = sum_k A[m][k]*Bt[n][k] + bias[n] (+skip).
// Tile (32*MT) x 128, K-chunk 32, cp.async 2-stage double buffer.
// 256 threads: warps 2(m) x 4(n); warp tile (16*MT) x 32.
template<int MT>
__global__ void __launch_bounds__(256, 2) k_gemm_tc(
        const float* __restrict__ A, int lda,
        const float* __restrict__ Bt, int Ktot,
        const float* __restrict__ bias,
        float* __restrict__ C, int ldc,
        const float* __restrict__ xskip) {
    extern __shared__ float sm[];
    const int AROWS = 32 * MT;                 // rows in A tile
    const int ATILE = AROWS * 36;              // floats per A buffer
    const int BTILE = 128 * 36;                // floats per B buffer
    float* As[2] = { sm, sm + ATILE };
    float* Bs[2] = { sm + 2 * ATILE, sm + 2 * ATILE + BTILE };
    uint32_t sA0 = smem_u32(sm);

    int tid = threadIdx.x;
    int wid = tid >> 5, lane = tid & 31;
    int wm = wid >> 2, wn = wid & 3;
    int lr = lane >> 2, lc = lane & 3;
    int m0 = blockIdx.y * AROWS, n0 = blockIdx.x * 128;

    float acc[MT][4][4];
    #pragma unroll
    for (int i = 0; i < MT; i++)
        #pragma unroll
        for (int j = 0; j < 4; j++)
            #pragma unroll
            for (int r = 0; r < 4; r++) acc[i][j][r] = 0.f;

    int nch = Ktot >> 5;

    // async loader for chunk ch into buffer ch&1
    auto issue = [&](int ch) {
        int buf = ch & 1;
        int k0 = ch << 5;
        uint32_t baseA = sA0 + (uint32_t)(buf * ATILE) * 4u;
        uint32_t baseB = sA0 + (uint32_t)(2 * ATILE + buf * BTILE) * 4u;
        #pragma unroll
        for (int it = 0; it < MT; it++) {               // A: AROWS x 32
            int idx = it * 256 + tid;
            int row = idx >> 3, c4 = (idx & 7) * 4;
            int m = m0 + row;
            const float* pa = A + (size_t)(m < THW_ ? m : THW_ - 1) * lda + k0 + c4;
            cp16(baseA + (uint32_t)(row * 36 + c4) * 4u, pa, (m < THW_) ? 16 : 0);
        }
        #pragma unroll
        for (int it = 0; it < 4; it++) {                // B: 128 x 32
            int idx = it * 256 + tid;
            int row = idx >> 3, c4 = (idx & 7) * 4;
            const float* pb = Bt + (size_t)(n0 + row) * Ktot + k0 + c4;
            cp16(baseB + (uint32_t)(row * 36 + c4) * 4u, pb, 16);
        }
        CP_COMMIT();
    };

    issue(0);
    for (int ch = 0; ch < nch; ch++) {
        if (ch + 1 < nch) { issue(ch + 1); CP_WAIT1(); }
        else               CP_WAIT0();
        __syncthreads();
        const float* AsB = As[ch & 1];
        const float* BsB = Bs[ch & 1];
        #pragma unroll
        for (int ks = 0; ks < 4; ks++) {
            int kb = ks * 8;
            uint32_t af[MT][4], bf[4][2];
            #pragma unroll
            for (int mt = 0; mt < MT; mt++) {
                int r = wm * (16 * MT) + mt * 16 + lr;
                af[mt][0] = f2tf32(AsB[r * 36 + kb + lc]);
                af[mt][1] = f2tf32(AsB[(r + 8) * 36 + kb + lc]);
                af[mt][2] = f2tf32(AsB[r * 36 + kb + lc + 4]);
                af[mt][3] = f2tf32(AsB[(r + 8) * 36 + kb + lc + 4]);
            }
            #pragma unroll
            for (int nt = 0; nt < 4; nt++) {
                int r = wn * 32 + nt * 8 + lr;
                bf[nt][0] = f2tf32(BsB[r * 36 + kb + lc]);
                bf[nt][1] = f2tf32(BsB[r * 36 + kb + lc + 4]);
            }
            #pragma unroll
            for (int mt = 0; mt < MT; mt++)
                #pragma unroll
                for (int nt = 0; nt < 4; nt++)
                    mma_tf32(acc[mt][nt], af[mt], bf[nt]);
        }
        __syncthreads();
    }

    // epilogue: c0=(r,c), c1=(r,c+1), c2=(r+8,c), c3=(r+8,c+1)
    #pragma unroll
    for (int mt = 0; mt < MT; mt++) {
        #pragma unroll
        for (int half = 0; half < 2; half++) {
            int mrow = m0 + wm * (16 * MT) + mt * 16 + lr + half * 8;
            if (mrow >= THW_) continue;
            int t = mrow / HW_, hw = mrow % HW_;
            #pragma unroll
            for (int nt = 0; nt < 4; nt++) {
                int n = n0 + wn * 32 + nt * 8 + 2 * lc;
                float v0 = acc[mt][nt][half * 2 + 0] + bias[n];
                float v1 = acc[mt][nt][half * 2 + 1] + bias[n + 1];
                if (xskip) {
                    v0 += xskip[((size_t)t * DIM_ + n) * HW_ + hw];
                    v1 += xskip[((size_t)t * DIM_ + n + 1) * HW_ + hw];
                }
                *(float2*)(C + (size_t)mrow * ldc + n) = make_float2(v0, v1);
            }
        }
    }
}

// ===================== weight transposes =====================
__global__ void k_twf(const float* __restrict__ W) {   // [768][5376] -> [5376][768]
    __shared__ float tile[32][33];
    int nb = blockIdx.x * 32, kb = blockIdx.y * 32;
    int tx = threadIdx.x, ty = threadIdx.y;
    #pragma unroll
    for (int i = 0; i < 4; i++)
        tile[ty + i * 8][tx] = W[(size_t)(kb + ty + i * 8) * FUSEDN_ + nb + tx];
    __syncthreads();
    #pragma unroll
    for (int i = 0; i < 4; i++)
        g_WtF[(size_t)(nb + ty + i * 8) * DIM_ + kb + tx] = tile[tx][ty + i * 8];
}
__global__ void k_twfin(const float* __restrict__ Wout, const float* __restrict__ Wmlp) {
    __shared__ float tile[32][33];
    int nb = blockIdx.x * 32, kb = blockIdx.y * 32;
    int tx = threadIdx.x, ty = threadIdx.y;
    #pragma unroll
    for (int i = 0; i < 4; i++) {
        int kk = kb + ty + i * 8, n = nb + tx;
        tile[ty + i * 8][tx] = (kk < DIM_) ? Wout[(size_t)kk * DIM_ + n]
                                           : Wmlp[(size_t)(kk - DIM_) * DIM_ + n];
    }
    __syncthreads();
    #pragma unroll
    for (int i = 0; i < 4; i++)
        g_WtFin[(size_t)(nb + ty + i * 8) * KFIN_ + kb + tx] = tile[tx][ty + i * 8];
}

// ===================== elementwise / attention =====================
__global__ void k_mod(const float* __restrict__ emb, const float* __restrict__ w_mod,
                      const float* __restrict__ b_mod) {
    int t = blockIdx.y, col = blockIdx.x * 256 + threadIdx.x;
    __shared__ float se[EMB_];
    for (int k = threadIdx.x; k < EMB_; k += 256) {
        float e = emb[t * EMB_ + k];
        se[k] = e / (1.f + expf(-e));
    }
    __syncthreads();
    float acc = 0.f;
    #pragma unroll 8
    for (int k = 0; k < EMB_; k++) acc += se[k] * w_mod[k * (2 * DIM_) + col];
    g_mod[t * (2 * DIM_) + col] = acc + b_mod[col];
}

__global__ void k_lnmod(const float* __restrict__ x) {
    int p = blockIdx.x, t = p / HW_, hw = p % HW_;
    const float* xp = x + (size_t)t * DIM_ * HW_ + hw;
    int tid = threadIdx.x;
    float v[3], sum = 0.f, sq = 0.f;
    #pragma unroll
    for (int i = 0; i < 3; i++) {
        v[i] = xp[(size_t)(tid + i * 256) * HW_];
        sum += v[i]; sq += v[i] * v[i];
    }
    __shared__ float s1[256], s2[256];
    s1[tid] = sum; s2[tid] = sq;
    __syncthreads();
    for (int o = 128; o; o >>= 1) {
        if (tid < o) { s1[tid] += s1[tid + o]; s2[tid] += s2[tid + o]; }
        __syncthreads();
    }
    float mean = s1[0] * (1.f / 768.f);
    float var = s2[0] * (1.f / 768.f) - mean * mean;
    float rinv = rsqrtf(var + 1e-5f);
    #pragma unroll
    for (int i = 0; i < 3; i++) {
        int d = tid + i * 256;
        float sc = g_mod[t * 1536 + d], sh = g_mod[t * 1536 + 768 + d];
        g_h[(size_t)p * DIM_ + d] = (v[i] - mean) * rinv * (1.f + sc) + sh;
    }
}

__global__ void k_qk(const float* __restrict__ qn_w, const float* __restrict__ qn_b,
                     const float* __restrict__ kn_w, const float* __restrict__ kn_b) {
    int gw = (blockIdx.x * blockDim.x + threadIdx.x) >> 5;
    int lane = threadIdx.x & 31;
    if (gw >= THW_ * HEADS_) return;
    int p = gw / HEADS_, head = gw % HEADS_;
    int t = p / HW_, hw = p % HW_;
    int hh = hw / RES_, ww = hw % RES_;
    float coord = (lane < 8) ? (float)t : (lane < 16) ? (float)hh : (float)ww;
    float inv = powf(10000.f, -(float)(lane & 7) * 0.125f);
    float ang = coord * inv;
    float c = cosf(ang), s = sinf(ang);
    #pragma unroll
    for (int which = 0; which < 2; which++) {
        float* base = g_fused + (size_t)p * FUSEDN_ + which * 768 + head * DH_;
        float x1 = 0.f, x2 = 0.f;
        if (lane < 24) { x1 = base[2 * lane]; x2 = base[2 * lane + 1]; }
        float sum = x1 + x2, sq = x1 * x1 + x2 * x2;
        #pragma unroll
        for (int o = 16; o; o >>= 1) {
            sum += __shfl_xor_sync(0xffffffffu, sum, o);
            sq  += __shfl_xor_sync(0xffffffffu, sq, o);
        }
        float mean = sum * (1.f / 48.f);
        float var = sq * (1.f / 48.f) - mean * mean;
        float rinv = rsqrtf(var + 1e-5f);
        if (lane < 24) {
            const float* w = which ? kn_w : qn_w;
            const float* b = which ? kn_b : qn_b;
            float y1 = (x1 - mean) * rinv * w[2 * lane]     + b[2 * lane];
            float y2 = (x2 - mean) * rinv * w[2 * lane + 1] + b[2 * lane + 1];
            float o1 = y1 * c - y2 * s;
            float o2 = y1 * s + y2 * c;
            if (which == 0) { o1 *= 0.14433756729740643f; o2 *= 0.14433756729740643f; }
            base[2 * lane] = o1; base[2 * lane + 1] = o2;
        }
    }
}

__global__ void k_attn() {
    int warp = threadIdx.x >> 5, lane = threadIdx.x & 31;
    int gw = blockIdx.x * 8 + warp;
    if (gw >= THW_ * HEADS_) return;
    int head = gw % HEADS_, p = gw / HEADS_;
    int hw = p % HW_;
    int h = hw / RES_, w = hw % RES_;
    __shared__ float ssc[8][80];
    __shared__ int spk[8][80];
    float* sc = ssc[warp];
    int* pk = spk[warp];
    int h0 = min(max(h - 2, 0), RES_ - 5);
    int w0 = min(max(w - 2, 0), RES_ - 5);
    for (int j = lane; j < NBR_; j += 32) {
        int a = j / 25, r = j % 25, cc = r / 5, e = r % 5;
        pk[j] = (a * RES_ + h0 + cc) * RES_ + (w0 + e);
    }
    __syncwarp();
    const float* qp = g_fused + (size_t)p * FUSEDN_ + head * DH_;
    float qa = qp[lane];
    float qb = (lane < 16) ? qp[32 + lane] : 0.f;
    for (int j = 0; j < NBR_; j++) {
        const float* kp = g_fused + (size_t)pk[j] * FUSEDN_ + KOFF_ + head * DH_;
        float partial = qa * kp[lane];
        if (lane < 16) partial += qb * kp[32 + lane];
        #pragma unroll
        for (int o = 16; o; o >>= 1) partial += __shfl_xor_sync(0xffffffffu, partial, o);
        if (lane == 0) sc[j] = partial;
    }
    __syncwarp();
    float m = -1e30f;
    for (int j = lane; j < NBR_; j += 32) m = fmaxf(m, sc[j]);
    #pragma unroll
    for (int o = 16; o; o >>= 1) m = fmaxf(m, __shfl_xor_sync(0xffffffffu, m, o));
    float sum = 0.f;
    for (int j = lane; j < NBR_; j += 32) {
        float e = __expf(sc[j] - m);
        sc[j] = e; sum += e;
    }
    #pragma unroll
    for (int o = 16; o; o >>= 1) sum += __shfl_xor_sync(0xffffffffu, sum, o);
    float rs = 1.f / sum;
    for (int j = lane; j < NBR_; j += 32) sc[j] *= rs;
    __syncwarp();
    float acc_a = 0.f, acc_b = 0.f;
    for (int j = 0; j < NBR_; j++) {
        const float* vp = g_fused + (size_t)pk[j] * FUSEDN_ + VOFF_ + head * DH_;
        float pj = sc[j];
        acc_a += pj * vp[lane];
        if (lane < 16) acc_b += pj * vp[32 + lane];
    }
    g_afin[(size_t)p * KFIN_ + head * DH_ + lane] = acc_a;
    if (lane < 16) g_afin[(size_t)p * KFIN_ + head * DH_ + 32 + lane] = acc_b;
}

__global__ void k_silu() {
    int i = blockIdx.x * 256 + threadIdx.x;           // float4 index
    if (i < THW_ * MLP_ / 4) {
        int p = i / (MLP_ / 4), c = i % (MLP_ / 4);
        float4 v = *(const float4*)(g_fused + (size_t)p * FUSEDN_ + MLPOFF_ + c * 4);
        v.x = v.x / (1.f + expf(-v.x));
        v.y = v.y / (1.f + expf(-v.y));
        v.z = v.z / (1.f + expf(-v.z));
        v.w = v.w / (1.f + expf(-v.w));
        *(float4*)(g_afin + (size_t)p * KFIN_ + 768 + c * 4) = v;
    }
}

__global__ void k_out(float* __restrict__ out) {
    __shared__ float tile[32][33];
    int t = blockIdx.z;
    int hw0 = blockIdx.x * 32, d0 = blockIdx.y * 32;
    int tx = threadIdx.x, ty = threadIdx.y;
    #pragma unroll
    for (int i = 0; i < 4; i++)
        tile[ty + i * 8][tx] = g_y[((size_t)t * HW_ + hw0 + ty + i * 8) * DIM_ + d0 + tx];
    __syncthreads();
    #pragma unroll
    for (int i = 0; i < 4; i++)
        out[((size_t)t * DIM_ + d0 + ty + i * 8) * HW_ + hw0 + tx] = tile[tx][ty + i * 8];
}

// ===================== launch =====================
extern "C" void kernel_launch(void* const* d_in, const int* in_sizes, int n_in,
                              void* d_out, int out_size) {
    const float* x       = (const float*)d_in[0];
    const float* emb     = (const float*)d_in[1];
    const float* w_mod   = (const float*)d_in[2];
    const float* b_mod   = (const float*)d_in[3];
    const float* qn_w    = (const float*)d_in[4];
    const float* qn_b    = (const float*)d_in[5];
    const float* kn_w    = (const float*)d_in[6];
    const float* kn_b    = (const float*)d_in[7];
    const float* W_fused = (const float*)d_in[8];
    const float* b_fused = (const float*)d_in[9];
    const float* W_out   = (const float*)d_in[10];
    const float* W_mlp   = (const float*)d_in[11];
    const float* b_mlp   = (const float*)d_in[12];
    float* out = (float*)d_out;

    float* WtF;    cudaGetSymbolAddress((void**)&WtF, g_WtF);
    float* WtFin;  cudaGetSymbolAddress((void**)&WtFin, g_WtFin);
    float* gh;     cudaGetSymbolAddress((void**)&gh, g_h);
    float* gfused; cudaGetSymbolAddress((void**)&gfused, g_fused);
    float* gafin;  cudaGetSymbolAddress((void**)&gafin, g_afin);
    float* gy;     cudaGetSymbolAddress((void**)&gy, g_y);

    // dynamic smem sizes: MT=4 -> 2*(128*36 + 128*36)*4 = 73728 B
    //                     MT=2 -> 2*( 64*36 + 128*36)*4 = 55296 B
    const int smem4 = 2 * (128 * 36 + 128 * 36) * 4;
    const int smem2 = 2 * (64 * 36 + 128 * 36) * 4;
    static int attr_done = 0;
    if (!attr_done) {
        cudaFuncSetAttribute(k_gemm_tc<4>, cudaFuncAttributeMaxDynamicSharedMemorySize, smem4);
        cudaFuncSetAttribute(k_gemm_tc<2>, cudaFuncAttributeMaxDynamicSharedMemorySize, smem2);
        attr_done = 1;
    }

    k_mod<<<dim3(6, 3), 256>>>(emb, w_mod, b_mod);
    k_lnmod<<<THW_, 256>>>(x);
    k_twf<<<dim3(FUSEDN_ / 32, DIM_ / 32), dim3(32, 8)>>>(W_fused);
    k_twfin<<<dim3(DIM_ / 32, KFIN_ / 32), dim3(32, 8)>>>(W_out, W_mlp);
    // fused = h @ W_fused + b_fused   (1728 x 5376, K=768), tile 128x128
    k_gemm_tc<4><<<dim3(FUSEDN_ / 128, 14), 256, smem4>>>(gh, DIM_, WtF, DIM_, b_fused,
                                                          gfused, FUSEDN_, nullptr);
    k_qk<<<(THW_ * HEADS_) / 8, 256>>>(qn_w, qn_b, kn_w, kn_b);
    k_attn<<<(THW_ * HEADS_) / 8, 256>>>();
    k_silu<<<(THW_ * MLP_ / 4 + 255) / 256, 256>>>();
    // y = skip + xa@W_out + silu(mlp)@W_mlp + b_mlp   (1728 x 768, K=3840), tile 64x128
    k_gemm_tc<2><<<dim3(DIM_ / 128, 27), 256, smem2>>>(gafin, KFIN_, WtFin, KFIN_, b_mlp,
                                                       gy, DIM_, x);
    k_out<<<dim3(HW_ / 32, DIM_ / 32, T_), dim3(32, 8)>>>(out);
}

// round 7
// speedup vs baseline: 2.7154x; 1.3954x over previous
#include <cuda_runtime.h>
#include <cuda_fp16.h>
#include <math.h>
#include <stdint.h>

// ---- fixed problem shape (B=1) ----
#define T_      3
#define RES_    24
#define HW_     576
#define THW_    1728
#define DIM_    768
#define HEADS_  16
#define DH_     48
#define EMB_    1024
#define MLP_    3072
#define FUSEDN_ 5376
#define KOFF_   768
#define VOFF_   1536
#define MLPOFF_ 2304
#define NBR_    75
#define KFIN_   3840         // 768 + 3072

// ---- scratch ----
__device__ __align__(16) float  g_mod[T_ * 2 * DIM_];
__device__ __align__(16) __half g_h[THW_ * DIM_];            // LN-mod activations (half)
__device__ __align__(16) float  g_fused[THW_ * FUSEDN_];     // q|k|v|mlp_h (fp32)
__device__ __align__(16) __half g_afin[THW_ * KFIN_];        // [xa | silu(mlp_h)] (half)
__device__ __align__(16) float  g_y[THW_ * DIM_];
__device__ __align__(16) __half g_WtF[FUSEDN_ * DIM_];       // W_fused^T (half)
__device__ __align__(16) __half g_WtFin[DIM_ * KFIN_];       // [Wout^T|Wmlp^T] (half)

__device__ __forceinline__ uint32_t smem_u32(const void* p) {
    uint32_t a;
    asm("{ .reg .u64 t; cvta.to.shared.u64 t, %1; cvt.u32.u64 %0, t; }" : "=r"(a) : "l"(p));
    return a;
}
__device__ __forceinline__ void cp16(uint32_t dst, const void* src, int srcsize) {
    asm volatile("cp.async.cg.shared.global [%0], [%1], 16, %2;"
                 :: "r"(dst), "l"(src), "r"(srcsize));
}
#define CP_COMMIT() asm volatile("cp.async.commit_group;" ::: "memory")
#define CP_WAIT0()  asm volatile("cp.async.wait_group 0;" ::: "memory")
#define CP_WAIT1()  asm volatile("cp.async.wait_group 1;" ::: "memory")

__device__ __forceinline__ void ldsm_x4(uint32_t& r0, uint32_t& r1, uint32_t& r2, uint32_t& r3,
                                        uint32_t addr) {
    asm volatile("ldmatrix.sync.aligned.m8n8.x4.shared.b16 {%0,%1,%2,%3}, [%4];"
                 : "=r"(r0), "=r"(r1), "=r"(r2), "=r"(r3) : "r"(addr));
}
__device__ __forceinline__ void mma_f16(float* c, const uint32_t* a, const uint32_t* b) {
    asm volatile(
        "mma.sync.aligned.m16n8k16.row.col.f32.f16.f16.f32 "
        "{%0,%1,%2,%3}, {%4,%5,%6,%7}, {%8,%9}, {%0,%1,%2,%3};"
        : "+f"(c[0]), "+f"(c[1]), "+f"(c[2]), "+f"(c[3])
        : "r"(a[0]), "r"(a[1]), "r"(a[2]), "r"(a[3]), "r"(b[0]), "r"(b[1]));
}

// ===================== pipelined fp16 tensor-core GEMM =====================
// C[m][n] = sum_k A[m][k]*Bt[n][k] + bias[n] (+skip). fp32 accum.
// Tile (32*MT) x 128, K-chunk 32, cp.async double buffer, ldmatrix frags.
// 256 threads: warps 2(m) x 4(n); warp tile (16*MT) x 32.
#define ROWH 40   // halfs per smem row (32 data + 8 pad); 80B, ldmatrix conflict-free
template<int MT>
__global__ void __launch_bounds__(256, 2) k_gemm_tc(
        const __half* __restrict__ A, int lda,
        const __half* __restrict__ Bt, int Ktot,
        const float* __restrict__ bias,
        float* __restrict__ C, int ldc,
        const float* __restrict__ xskip) {
    extern __shared__ __half smh[];
    const int AROWS = 32 * MT;
    const int ATILE = AROWS * ROWH;            // halfs per A buffer
    const int BTILE = 128 * ROWH;              // halfs per B buffer
    uint32_t s0 = smem_u32(smh);

    int tid = threadIdx.x;
    int wid = tid >> 5, lane = tid & 31;
    int wm = wid >> 2, wn = wid & 3;
    int lr = lane >> 2, lc = lane & 3;
    int m0 = blockIdx.y * AROWS, n0 = blockIdx.x * 128;

    float acc[MT][4][4];
    #pragma unroll
    for (int i = 0; i < MT; i++)
        #pragma unroll
        for (int j = 0; j < 4; j++)
            #pragma unroll
            for (int r = 0; r < 4; r++) acc[i][j][r] = 0.f;

    int nch = Ktot >> 5;

    auto issue = [&](int ch) {
        int buf = ch & 1;
        int k0 = ch << 5;
        uint32_t baseA = s0 + (uint32_t)(buf * ATILE) * 2u;
        uint32_t baseB = s0 + (uint32_t)((2 * ATILE) + buf * BTILE) * 2u;
        // A: AROWS rows x 4 granules (16B = 8 halfs)
        #pragma unroll
        for (int it = 0; it < MT / 2; it++) {
            int idx = it * 256 + tid;
            int row = idx >> 2, g = idx & 3;
            int m = m0 + row;
            const __half* pa = A + (size_t)(m < THW_ ? m : THW_ - 1) * lda + k0 + g * 8;
            cp16(baseA + (uint32_t)(row * ROWH + g * 8) * 2u, pa, (m < THW_) ? 16 : 0);
        }
        // B: 128 rows x 4 granules
        #pragma unroll
        for (int it = 0; it < 2; it++) {
            int idx = it * 256 + tid;
            int row = idx >> 2, g = idx & 3;
            const __half* pb = Bt + (size_t)(n0 + row) * Ktot + k0 + g * 8;
            cp16(baseB + (uint32_t)(row * ROWH + g * 8) * 2u, pb, 16);
        }
        CP_COMMIT();
    };

    issue(0);
    for (int ch = 0; ch < nch; ch++) {
        if (ch + 1 < nch) { issue(ch + 1); CP_WAIT1(); }
        else               CP_WAIT0();
        __syncthreads();
        int buf = ch & 1;
        uint32_t baseA = s0 + (uint32_t)(buf * ATILE) * 2u;
        uint32_t baseB = s0 + (uint32_t)((2 * ATILE) + buf * BTILE) * 2u;

        #pragma unroll
        for (int ks = 0; ks < 2; ks++) {       // two k16 steps per 32-chunk
            uint32_t af[MT][4], bf[4][2];
            // A frags: ldmatrix.x4 per 16-row tile
            #pragma unroll
            for (int mt = 0; mt < MT; mt++) {
                int r = wm * (16 * MT) + mt * 16 + (lane & 15);
                uint32_t addr = baseA + (uint32_t)(r * ROWH + ks * 16 + (lane >> 4) * 8) * 2u;
                ldsm_x4(af[mt][0], af[mt][1], af[mt][2], af[mt][3], addr);
            }
            // B frags: ldmatrix.x4 covers two n8 tiles (nt, nt+1)
            #pragma unroll
            for (int np = 0; np < 2; np++) {
                int q = lane >> 3;             // 0..3
                int r = wn * 32 + (np * 2 + (q >> 1)) * 8 + (lane & 7);
                uint32_t addr = baseB + (uint32_t)(r * ROWH + ks * 16 + (q & 1) * 8) * 2u;
                ldsm_x4(bf[np * 2][0], bf[np * 2][1], bf[np * 2 + 1][0], bf[np * 2 + 1][1], addr);
            }
            #pragma unroll
            for (int mt = 0; mt < MT; mt++)
                #pragma unroll
                for (int nt = 0; nt < 4; nt++)
                    mma_f16(acc[mt][nt], af[mt], bf[nt]);
        }
        __syncthreads();
    }

    // epilogue: c0=(r,c), c1=(r,c+1), c2=(r+8,c), c3=(r+8,c+1)
    #pragma unroll
    for (int mt = 0; mt < MT; mt++) {
        #pragma unroll
        for (int half = 0; half < 2; half++) {
            int mrow = m0 + wm * (16 * MT) + mt * 16 + lr + half * 8;
            if (mrow >= THW_) continue;
            int t = mrow / HW_, hw = mrow % HW_;
            #pragma unroll
            for (int nt = 0; nt < 4; nt++) {
                int n = n0 + wn * 32 + nt * 8 + 2 * lc;
                float v0 = acc[mt][nt][half * 2 + 0] + bias[n];
                float v1 = acc[mt][nt][half * 2 + 1] + bias[n + 1];
                if (xskip) {
                    v0 += xskip[((size_t)t * DIM_ + n) * HW_ + hw];
                    v1 += xskip[((size_t)t * DIM_ + n + 1) * HW_ + hw];
                }
                *(float2*)(C + (size_t)mrow * ldc + n) = make_float2(v0, v1);
            }
        }
    }
}

// ===================== weight transposes (fp32 -> half) =====================
__global__ void k_twf(const float* __restrict__ W) {   // [768][5376] -> half [5376][768]
    __shared__ float tile[32][33];
    int nb = blockIdx.x * 32, kb = blockIdx.y * 32;
    int tx = threadIdx.x, ty = threadIdx.y;
    #pragma unroll
    for (int i = 0; i < 4; i++)
        tile[ty + i * 8][tx] = W[(size_t)(kb + ty + i * 8) * FUSEDN_ + nb + tx];
    __syncthreads();
    #pragma unroll
    for (int i = 0; i < 4; i++)
        g_WtF[(size_t)(nb + ty + i * 8) * DIM_ + kb + tx] = __float2half(tile[tx][ty + i * 8]);
}
__global__ void k_twfin(const float* __restrict__ Wout, const float* __restrict__ Wmlp) {
    __shared__ float tile[32][33];
    int nb = blockIdx.x * 32, kb = blockIdx.y * 32;
    int tx = threadIdx.x, ty = threadIdx.y;
    #pragma unroll
    for (int i = 0; i < 4; i++) {
        int kk = kb + ty + i * 8, n = nb + tx;
        tile[ty + i * 8][tx] = (kk < DIM_) ? Wout[(size_t)kk * DIM_ + n]
                                           : Wmlp[(size_t)(kk - DIM_) * DIM_ + n];
    }
    __syncthreads();
    #pragma unroll
    for (int i = 0; i < 4; i++)
        g_WtFin[(size_t)(nb + ty + i * 8) * KFIN_ + kb + tx] = __float2half(tile[tx][ty + i * 8]);
}

// ===================== elementwise / attention =====================
__global__ void k_mod(const float* __restrict__ emb, const float* __restrict__ w_mod,
                      const float* __restrict__ b_mod) {
    int t = blockIdx.y, col = blockIdx.x * 256 + threadIdx.x;
    __shared__ float se[EMB_];
    for (int k = threadIdx.x; k < EMB_; k += 256) {
        float e = emb[t * EMB_ + k];
        se[k] = e / (1.f + expf(-e));
    }
    __syncthreads();
    float acc = 0.f;
    #pragma unroll 8
    for (int k = 0; k < EMB_; k++) acc += se[k] * w_mod[k * (2 * DIM_) + col];
    g_mod[t * (2 * DIM_) + col] = acc + b_mod[col];
}

__global__ void k_lnmod(const float* __restrict__ x) {
    int p = blockIdx.x, t = p / HW_, hw = p % HW_;
    const float* xp = x + (size_t)t * DIM_ * HW_ + hw;
    int tid = threadIdx.x;
    float v[3], sum = 0.f, sq = 0.f;
    #pragma unroll
    for (int i = 0; i < 3; i++) {
        v[i] = xp[(size_t)(tid + i * 256) * HW_];
        sum += v[i]; sq += v[i] * v[i];
    }
    __shared__ float s1[256], s2[256];
    s1[tid] = sum; s2[tid] = sq;
    __syncthreads();
    for (int o = 128; o; o >>= 1) {
        if (tid < o) { s1[tid] += s1[tid + o]; s2[tid] += s2[tid + o]; }
        __syncthreads();
    }
    float mean = s1[0] * (1.f / 768.f);
    float var = s2[0] * (1.f / 768.f) - mean * mean;
    float rinv = rsqrtf(var + 1e-5f);
    #pragma unroll
    for (int i = 0; i < 3; i++) {
        int d = tid + i * 256;
        float sc = g_mod[t * 1536 + d], sh = g_mod[t * 1536 + 768 + d];
        g_h[(size_t)p * DIM_ + d] = __float2half((v[i] - mean) * rinv * (1.f + sc) + sh);
    }
}

__global__ void k_qk(const float* __restrict__ qn_w, const float* __restrict__ qn_b,
                     const float* __restrict__ kn_w, const float* __restrict__ kn_b) {
    int gw = (blockIdx.x * blockDim.x + threadIdx.x) >> 5;
    int lane = threadIdx.x & 31;
    if (gw >= THW_ * HEADS_) return;
    int p = gw / HEADS_, head = gw % HEADS_;
    int t = p / HW_, hw = p % HW_;
    int hh = hw / RES_, ww = hw % RES_;
    float coord = (lane < 8) ? (float)t : (lane < 16) ? (float)hh : (float)ww;
    float inv = powf(10000.f, -(float)(lane & 7) * 0.125f);
    float ang = coord * inv;
    float c = cosf(ang), s = sinf(ang);
    #pragma unroll
    for (int which = 0; which < 2; which++) {
        float* base = g_fused + (size_t)p * FUSEDN_ + which * 768 + head * DH_;
        float x1 = 0.f, x2 = 0.f;
        if (lane < 24) { x1 = base[2 * lane]; x2 = base[2 * lane + 1]; }
        float sum = x1 + x2, sq = x1 * x1 + x2 * x2;
        #pragma unroll
        for (int o = 16; o; o >>= 1) {
            sum += __shfl_xor_sync(0xffffffffu, sum, o);
            sq  += __shfl_xor_sync(0xffffffffu, sq, o);
        }
        float mean = sum * (1.f / 48.f);
        float var = sq * (1.f / 48.f) - mean * mean;
        float rinv = rsqrtf(var + 1e-5f);
        if (lane < 24) {
            const float* w = which ? kn_w : qn_w;
            const float* b = which ? kn_b : qn_b;
            float y1 = (x1 - mean) * rinv * w[2 * lane]     + b[2 * lane];
            float y2 = (x2 - mean) * rinv * w[2 * lane + 1] + b[2 * lane + 1];
            float o1 = y1 * c - y2 * s;
            float o2 = y1 * s + y2 * c;
            if (which == 0) { o1 *= 0.14433756729740643f; o2 *= 0.14433756729740643f; }
            base[2 * lane] = o1; base[2 * lane + 1] = o2;
        }
    }
}

__global__ void k_attn() {
    int warp = threadIdx.x >> 5, lane = threadIdx.x & 31;
    int gw = blockIdx.x * 8 + warp;
    if (gw >= THW_ * HEADS_) return;
    int head = gw % HEADS_, p = gw / HEADS_;
    int hw = p % HW_;
    int h = hw / RES_, w = hw % RES_;
    __shared__ float ssc[8][80];
    __shared__ int spk[8][80];
    float* sc = ssc[warp];
    int* pk = spk[warp];
    int h0 = min(max(h - 2, 0), RES_ - 5);
    int w0 = min(max(w - 2, 0), RES_ - 5);
    for (int j = lane; j < NBR_; j += 32) {
        int a = j / 25, r = j % 25, cc = r / 5, e = r % 5;
        pk[j] = (a * RES_ + h0 + cc) * RES_ + (w0 + e);
    }
    __syncwarp();
    const float* qp = g_fused + (size_t)p * FUSEDN_ + head * DH_;
    float qa = qp[lane];
    float qb = (lane < 16) ? qp[32 + lane] : 0.f;
    for (int j = 0; j < NBR_; j++) {
        const float* kp = g_fused + (size_t)pk[j] * FUSEDN_ + KOFF_ + head * DH_;
        float partial = qa * kp[lane];
        if (lane < 16) partial += qb * kp[32 + lane];
        #pragma unroll
        for (int o = 16; o; o >>= 1) partial += __shfl_xor_sync(0xffffffffu, partial, o);
        if (lane == 0) sc[j] = partial;
    }
    __syncwarp();
    float m = -1e30f;
    for (int j = lane; j < NBR_; j += 32) m = fmaxf(m, sc[j]);
    #pragma unroll
    for (int o = 16; o; o >>= 1) m = fmaxf(m, __shfl_xor_sync(0xffffffffu, m, o));
    float sum = 0.f;
    for (int j = lane; j < NBR_; j += 32) {
        float e = __expf(sc[j] - m);
        sc[j] = e; sum += e;
    }
    #pragma unroll
    for (int o = 16; o; o >>= 1) sum += __shfl_xor_sync(0xffffffffu, sum, o);
    float rs = 1.f / sum;
    for (int j = lane; j < NBR_; j += 32) sc[j] *= rs;
    __syncwarp();
    float acc_a = 0.f, acc_b = 0.f;
    for (int j = 0; j < NBR_; j++) {
        const float* vp = g_fused + (size_t)pk[j] * FUSEDN_ + VOFF_ + head * DH_;
        float pj = sc[j];
        acc_a += pj * vp[lane];
        if (lane < 16) acc_b += pj * vp[32 + lane];
    }
    g_afin[(size_t)p * KFIN_ + head * DH_ + lane] = __float2half(acc_a);
    if (lane < 16) g_afin[(size_t)p * KFIN_ + head * DH_ + 32 + lane] = __float2half(acc_b);
}

__global__ void k_silu() {
    int i = blockIdx.x * 256 + threadIdx.x;           // float4 index
    if (i < THW_ * MLP_ / 4) {
        int p = i / (MLP_ / 4), c = i % (MLP_ / 4);
        float4 v = *(const float4*)(g_fused + (size_t)p * FUSEDN_ + MLPOFF_ + c * 4);
        v.x = v.x / (1.f + expf(-v.x));
        v.y = v.y / (1.f + expf(-v.y));
        v.z = v.z / (1.f + expf(-v.z));
        v.w = v.w / (1.f + expf(-v.w));
        __half2 h0 = __floats2half2_rn(v.x, v.y);
        __half2 h1 = __floats2half2_rn(v.z, v.w);
        *(__half2*)(g_afin + (size_t)p * KFIN_ + 768 + c * 4)     = h0;
        *(__half2*)(g_afin + (size_t)p * KFIN_ + 768 + c * 4 + 2) = h1;
    }
}

__global__ void k_out(float* __restrict__ out) {
    __shared__ float tile[32][33];
    int t = blockIdx.z;
    int hw0 = blockIdx.x * 32, d0 = blockIdx.y * 32;
    int tx = threadIdx.x, ty = threadIdx.y;
    #pragma unroll
    for (int i = 0; i < 4; i++)
        tile[ty + i * 8][tx] = g_y[((size_t)t * HW_ + hw0 + ty + i * 8) * DIM_ + d0 + tx];
    __syncthreads();
    #pragma unroll
    for (int i = 0; i < 4; i++)
        out[((size_t)t * DIM_ + d0 + ty + i * 8) * HW_ + hw0 + tx] = tile[tx][ty + i * 8];
}

// ===================== launch =====================
extern "C" void kernel_launch(void* const* d_in, const int* in_sizes, int n_in,
                              void* d_out, int out_size) {
    const float* x       = (const float*)d_in[0];
    const float* emb     = (const float*)d_in[1];
    const float* w_mod   = (const float*)d_in[2];
    const float* b_mod   = (const float*)d_in[3];
    const float* qn_w    = (const float*)d_in[4];
    const float* qn_b    = (const float*)d_in[5];
    const float* kn_w    = (const float*)d_in[6];
    const float* kn_b    = (const float*)d_in[7];
    const float* W_fused = (const float*)d_in[8];
    const float* b_fused = (const float*)d_in[9];
    const float* W_out   = (const float*)d_in[10];
    const float* W_mlp   = (const float*)d_in[11];
    const float* b_mlp   = (const float*)d_in[12];
    float* out = (float*)d_out;

    __half* WtF;   cudaGetSymbolAddress((void**)&WtF, g_WtF);
    __half* WtFin; cudaGetSymbolAddress((void**)&WtFin, g_WtFin);
    __half* gh;    cudaGetSymbolAddress((void**)&gh, g_h);
    float* gfused; cudaGetSymbolAddress((void**)&gfused, g_fused);
    __half* gafin; cudaGetSymbolAddress((void**)&gafin, g_afin);
    float* gy;     cudaGetSymbolAddress((void**)&gy, g_y);

    // dynamic smem: MT=4 -> 2*(128*40 + 128*40)*2 = 40960 B
    //               MT=2 -> 2*( 64*40 + 128*40)*2 = 30720 B
    const int smem4 = 2 * (128 * ROWH + 128 * ROWH) * 2;
    const int smem2 = 2 * (64 * ROWH + 128 * ROWH) * 2;
    static int attr_done = 0;
    if (!attr_done) {
        cudaFuncSetAttribute(k_gemm_tc<4>, cudaFuncAttributeMaxDynamicSharedMemorySize, smem4);
        cudaFuncSetAttribute(k_gemm_tc<2>, cudaFuncAttributeMaxDynamicSharedMemorySize, smem2);
        attr_done = 1;
    }

    k_mod<<<dim3(6, 3), 256>>>(emb, w_mod, b_mod);
    k_lnmod<<<THW_, 256>>>(x);
    k_twf<<<dim3(FUSEDN_ / 32, DIM_ / 32), dim3(32, 8)>>>(W_fused);
    k_twfin<<<dim3(DIM_ / 32, KFIN_ / 32), dim3(32, 8)>>>(W_out, W_mlp);
    // fused = h @ W_fused + b_fused   (1728 x 5376, K=768), tile 128x128
    k_gemm_tc<4><<<dim3(FUSEDN_ / 128, 14), 256, smem4>>>(gh, DIM_, WtF, DIM_, b_fused,
                                                          gfused, FUSEDN_, nullptr);
    k_qk<<<(THW_ * HEADS_) / 8, 256>>>(qn_w, qn_b, kn_w, kn_b);
    k_attn<<<(THW_ * HEADS_) / 8, 256>>>();
    k_silu<<<(THW_ * MLP_ / 4 + 255) / 256, 256>>>();
    // y = skip + xa@W_out + silu(mlp)@W_mlp + b_mlp   (1728 x 768, K=3840), tile 64x128
    k_gemm_tc<2><<<dim3(DIM_ / 128, 27), 256, smem2>>>(gafin, KFIN_, WtFin, KFIN_, b_mlp,
                                                       gy, DIM_, x);
    k_out<<<dim3(HW_ / 32, DIM_ / 32, T_), dim3(32, 8)>>>(out);
}

// round 9
// speedup vs baseline: 3.0169x; 1.1110x over previous
#include <cuda_runtime.h>
#include <cuda_fp16.h>
#include <math.h>
#include <stdint.h>

// ---- fixed problem shape (B=1) ----
#define T_      3
#define RES_    24
#define HW_     576
#define THW_    1728
#define DIM_    768
#define HEADS_  16
#define DH_     48
#define EMB_    1024
#define MLP_    3072
#define FUSEDN_ 5376
#define QKVN_   2304
#define KOFF_   768
#define VOFF_   1536
#define NBR_    75
#define KFIN_   3840         // 768 + 3072

// ---- scratch ----
__device__ __align__(16) float  g_mod[T_ * 2 * DIM_];
__device__ __align__(16) float  g_stats[2 * THW_];           // [sum | sumsq]
__device__ __align__(16) __half g_h[THW_ * DIM_];            // LN-mod activations
__device__ __align__(16) float  g_fused[THW_ * QKVN_];       // q|k|v (fp32)
__device__ __align__(16) __half g_afin[THW_ * KFIN_];        // [xa | silu(mlp_h)]
__device__ __align__(16) __half g_WF[DIM_ * FUSEDN_];        // W_fused (half, [K][N])
__device__ __align__(16) __half g_WFin[KFIN_ * DIM_];        // [Wout;Wmlp] (half, [K][N])

__device__ __forceinline__ uint32_t smem_u32(const void* p) {
    uint32_t a;
    asm("{ .reg .u64 t; cvta.to.shared.u64 t, %1; cvt.u32.u64 %0, t; }" : "=r"(a) : "l"(p));
    return a;
}
__device__ __forceinline__ void cp16(uint32_t dst, const void* src, int srcsize) {
    asm volatile("cp.async.cg.shared.global [%0], [%1], 16, %2;"
                 :: "r"(dst), "l"(src), "r"(srcsize));
}
#define CP_COMMIT() asm volatile("cp.async.commit_group;" ::: "memory")
#define CP_WAIT0()  asm volatile("cp.async.wait_group 0;" ::: "memory")
#define CP_WAIT1()  asm volatile("cp.async.wait_group 1;" ::: "memory")

__device__ __forceinline__ void ldsm_x4(uint32_t& r0, uint32_t& r1, uint32_t& r2, uint32_t& r3,
                                        uint32_t addr) {
    asm volatile("ldmatrix.sync.aligned.m8n8.x4.shared.b16 {%0,%1,%2,%3}, [%4];"
                 : "=r"(r0), "=r"(r1), "=r"(r2), "=r"(r3) : "r"(addr));
}
__device__ __forceinline__ void ldsm_x4t(uint32_t& r0, uint32_t& r1, uint32_t& r2, uint32_t& r3,
                                         uint32_t addr) {
    asm volatile("ldmatrix.sync.aligned.m8n8.x4.trans.shared.b16 {%0,%1,%2,%3}, [%4];"
                 : "=r"(r0), "=r"(r1), "=r"(r2), "=r"(r3) : "r"(addr));
}
__device__ __forceinline__ void mma_f16(float* c, const uint32_t* a, const uint32_t* b) {
    asm volatile(
        "mma.sync.aligned.m16n8k16.row.col.f32.f16.f16.f32 "
        "{%0,%1,%2,%3}, {%4,%5,%6,%7}, {%8,%9}, {%0,%1,%2,%3};"
        : "+f"(c[0]), "+f"(c[1]), "+f"(c[2]), "+f"(c[3])
        : "r"(a[0]), "r"(a[1]), "r"(a[2]), "r"(a[3]), "r"(b[0]), "r"(b[1]));
}

#define ROWH 40    // A smem row: 32 halfs + 8 pad
#define ROWB 136   // B smem row: 128 halfs + 8 pad

// ===================== pipelined fp16 GEMM, B in [K][N] via ldmatrix.trans ======
// C = A[m][k] * B[k][n]. Tile (32*MT) x 128, K-chunk 32, cp.async double buffer.
// EPI 0: n<2304 -> g_fused fp32 (+bias); n>=2304 -> silu -> g_afin half (+bias).
// EPI 1: smem-transpose epilogue -> out[t][n][hw] = acc + bias[n] + x[t][n][hw].
template<int MT, int EPI>
__global__ void __launch_bounds__(256, 2) k_gemm(
        const __half* __restrict__ A, int lda,
        const __half* __restrict__ B, int ldb, int Ktot,
        const float* __restrict__ bias,
        float* __restrict__ Cq, __half* __restrict__ afin,
        float* __restrict__ outp, const float* __restrict__ x) {
    extern __shared__ __half smh[];
    const int AROWS = 32 * MT;
    const int ATILE = AROWS * ROWH;
    const int BTILE = 32 * ROWB;
    uint32_t s0 = smem_u32(smh);

    int tid = threadIdx.x;
    int wid = tid >> 5, lane = tid & 31;
    int wm = wid >> 2, wn = wid & 3;
    int lr = lane >> 2, lc = lane & 3;
    int m0 = blockIdx.y * AROWS, n0 = blockIdx.x * 128;

    float acc[MT][4][4];
    #pragma unroll
    for (int i = 0; i < MT; i++)
        #pragma unroll
        for (int j = 0; j < 4; j++)
            #pragma unroll
            for (int r = 0; r < 4; r++) acc[i][j][r] = 0.f;

    int nch = Ktot >> 5;

    auto issue = [&](int ch) {
        int buf = ch & 1;
        int k0 = ch << 5;
        uint32_t baseA = s0 + (uint32_t)(buf * ATILE) * 2u;
        uint32_t baseB = s0 + (uint32_t)((2 * ATILE) + buf * BTILE) * 2u;
        #pragma unroll
        for (int it = 0; it < MT / 2; it++) {     // A: AROWS x 32 (4 granules/row)
            int idx = it * 256 + tid;
            int row = idx >> 2, g = idx & 3;
            int m = m0 + row;
            const __half* pa = A + (size_t)(m < THW_ ? m : THW_ - 1) * lda + k0 + g * 8;
            cp16(baseA + (uint32_t)(row * ROWH + g * 8) * 2u, pa, (m < THW_) ? 16 : 0);
        }
        #pragma unroll
        for (int it = 0; it < 2; it++) {          // B: 32 rows x 128 (16 granules/row)
            int idx = it * 256 + tid;
            int row = idx >> 4, g = idx & 15;
            const __half* pb = B + (size_t)(k0 + row) * ldb + n0 + g * 8;
            cp16(baseB + (uint32_t)(row * ROWB + g * 8) * 2u, pb, 16);
        }
        CP_COMMIT();
    };

    issue(0);
    for (int ch = 0; ch < nch; ch++) {
        if (ch + 1 < nch) { issue(ch + 1); CP_WAIT1(); }
        else               CP_WAIT0();
        __syncthreads();
        int buf = ch & 1;
        uint32_t baseA = s0 + (uint32_t)(buf * ATILE) * 2u;
        uint32_t baseB = s0 + (uint32_t)((2 * ATILE) + buf * BTILE) * 2u;

        #pragma unroll
        for (int ks = 0; ks < 2; ks++) {
            uint32_t af[MT][4], bf[4][2];
            #pragma unroll
            for (int mt = 0; mt < MT; mt++) {     // A frags (non-trans, [m][k] smem)
                int r = wm * (16 * MT) + mt * 16 + (lane & 15);
                uint32_t addr = baseA + (uint32_t)(r * ROWH + ks * 16 + (lane >> 4) * 8) * 2u;
                ldsm_x4(af[mt][0], af[mt][1], af[mt][2], af[mt][3], addr);
            }
            #pragma unroll
            for (int np = 0; np < 2; np++) {      // B frags (trans, [k][n] smem)
                int q = lane >> 3;                // 0..3: (k-half, n-tile)
                int kr = ks * 16 + (q & 1) * 8 + (lane & 7);
                int nc = wn * 32 + (np * 2 + (q >> 1)) * 8;
                uint32_t addr = baseB + (uint32_t)(kr * ROWB + nc) * 2u;
                ldsm_x4t(bf[np * 2][0], bf[np * 2][1], bf[np * 2 + 1][0], bf[np * 2 + 1][1], addr);
            }
            #pragma unroll
            for (int mt = 0; mt < MT; mt++)
                #pragma unroll
                for (int nt = 0; nt < 4; nt++)
                    mma_f16(acc[mt][nt], af[mt], bf[nt]);
        }
        __syncthreads();
    }

    if (EPI == 0) {
        bool is_mlp = (n0 >= QKVN_);
        #pragma unroll
        for (int mt = 0; mt < MT; mt++) {
            #pragma unroll
            for (int hf = 0; hf < 2; hf++) {
                int mrow = m0 + wm * (16 * MT) + mt * 16 + lr + hf * 8;
                if (mrow >= THW_) continue;
                #pragma unroll
                for (int nt = 0; nt < 4; nt++) {
                    int n = n0 + wn * 32 + nt * 8 + 2 * lc;
                    float v0 = acc[mt][nt][hf * 2 + 0] + bias[n];
                    float v1 = acc[mt][nt][hf * 2 + 1] + bias[n + 1];
                    if (is_mlp) {
                        v0 = v0 / (1.f + expf(-v0));
                        v1 = v1 / (1.f + expf(-v1));
                        *(__half2*)(afin + (size_t)mrow * KFIN_ + 768 + (n - QKVN_)) =
                            __floats2half2_rn(v0, v1);
                    } else {
                        *(float2*)(Cq + (size_t)mrow * QKVN_ + n) = make_float2(v0, v1);
                    }
                }
            }
        }
    } else {
        // stage 64x128 tile in smem as [n][m], then write coalesced along hw
        float* st = (float*)smh;
        #pragma unroll
        for (int mt = 0; mt < MT; mt++) {
            #pragma unroll
            for (int hf = 0; hf < 2; hf++) {
                int ml = wm * (16 * MT) + mt * 16 + lr + hf * 8;
                #pragma unroll
                for (int nt = 0; nt < 4; nt++) {
                    int nl = wn * 32 + nt * 8 + 2 * lc;
                    st[nl * 65 + ml]       = acc[mt][nt][hf * 2 + 0];
                    st[(nl + 1) * 65 + ml] = acc[mt][nt][hf * 2 + 1];
                }
            }
        }
        __syncthreads();
        int t = m0 / HW_, hw0 = m0 % HW_;
        int nr = tid >> 1, mh = (tid & 1) * 32;
        int n = n0 + nr;
        float bb = bias[n];
        const float* xrow = x + ((size_t)t * DIM_ + n) * HW_ + hw0 + mh;
        float* orow = outp + ((size_t)t * DIM_ + n) * HW_ + hw0 + mh;
        #pragma unroll
        for (int i = 0; i < 8; i++) {
            float4 xs = *(const float4*)(xrow + i * 4);
            float4 o;
            o.x = st[nr * 65 + mh + i * 4 + 0] + bb + xs.x;
            o.y = st[nr * 65 + mh + i * 4 + 1] + bb + xs.y;
            o.z = st[nr * 65 + mh + i * 4 + 2] + bb + xs.z;
            o.w = st[nr * 65 + mh + i * 4 + 3] + bb + xs.w;
            *(float4*)(orow + i * 4) = o;
        }
    }
}

// ===================== weight converts (fp32 -> half, layout preserved) ========
__global__ void k_cvtWF(const float* __restrict__ W) {      // [768][5376]
    int i = blockIdx.x * 256 + threadIdx.x;                 // 8-elem granule
    if (i < DIM_ * FUSEDN_ / 8) {
        float4 a = *(const float4*)(W + (size_t)i * 8);
        float4 b = *(const float4*)(W + (size_t)i * 8 + 4);
        __half2 h[4] = { __floats2half2_rn(a.x, a.y), __floats2half2_rn(a.z, a.w),
                         __floats2half2_rn(b.x, b.y), __floats2half2_rn(b.z, b.w) };
        *(uint2*)(g_WF + (size_t)i * 8)     = *(uint2*)&h[0];
        *(uint2*)(g_WF + (size_t)i * 8 + 4) = *(uint2*)&h[2];
    }
}
__global__ void k_cvtWFin(const float* __restrict__ Wout, const float* __restrict__ Wmlp) {
    int i = blockIdx.x * 256 + threadIdx.x;
    const int N1 = DIM_ * DIM_ / 8;                         // W_out granules
    if (i < KFIN_ * DIM_ / 8) {
        const float* src = (i < N1) ? (Wout + (size_t)i * 8)
                                    : (Wmlp + (size_t)(i - N1) * 8);
        float4 a = *(const float4*)(src);
        float4 b = *(const float4*)(src + 4);
        __half2 h[4] = { __floats2half2_rn(a.x, a.y), __floats2half2_rn(a.z, a.w),
                         __floats2half2_rn(b.x, b.y), __floats2half2_rn(b.z, b.w) };
        *(uint2*)(g_WFin + (size_t)i * 8)     = *(uint2*)&h[0];
        *(uint2*)(g_WFin + (size_t)i * 8 + 4) = *(uint2*)&h[2];
    }
}

// ===================== modulation / LN =====================
__global__ void k_mod(const float* __restrict__ emb, const float* __restrict__ w_mod,
                      const float* __restrict__ b_mod) {
    int t = blockIdx.y, col = blockIdx.x * 256 + threadIdx.x;
    __shared__ float se[EMB_];
    for (int k = threadIdx.x; k < EMB_; k += 256) {
        float e = emb[t * EMB_ + k];
        se[k] = e / (1.f + expf(-e));
    }
    __syncthreads();
    float acc = 0.f;
    #pragma unroll 8
    for (int k = 0; k < EMB_; k++) acc += se[k] * w_mod[k * (2 * DIM_) + col];
    g_mod[t * (2 * DIM_) + col] = acc + b_mod[col];
}

__global__ void k_stats(const float* __restrict__ x) {      // coalesced LN stats
    int t = blockIdx.y, d0 = blockIdx.x * 96;
    int hw = threadIdx.x;
    float s = 0.f, q = 0.f;
    const float* xp = x + ((size_t)t * DIM_ + d0) * HW_ + hw;
    #pragma unroll 8
    for (int i = 0; i < 96; i++) {
        float v = xp[(size_t)i * HW_];
        s += v; q += v * v;
    }
    atomicAdd(&g_stats[t * HW_ + hw], s);
    atomicAdd(&g_stats[THW_ + t * HW_ + hw], q);
}

__global__ void k_applyT(const float* __restrict__ x) {     // transpose + LN + mod
    __shared__ float tile[32][33];
    int t = blockIdx.z;
    int hw0 = blockIdx.x * 32, d0 = blockIdx.y * 32;
    int tx = threadIdx.x, ty = threadIdx.y;
    #pragma unroll
    for (int i = 0; i < 4; i++)
        tile[ty + i * 8][tx] = x[((size_t)t * DIM_ + d0 + ty + i * 8) * HW_ + hw0 + tx];
    __syncthreads();
    int d = d0 + tx;
    float sc = 1.f + g_mod[t * 1536 + d];
    float sh = g_mod[t * 1536 + 768 + d];
    #pragma unroll
    for (int i = 0; i < 4; i++) {
        int hw = hw0 + ty + i * 8;
        int p = t * HW_ + hw;
        float sum = g_stats[p], sq = g_stats[THW_ + p];
        float mean = sum * (1.f / 768.f);
        float var = sq * (1.f / 768.f) - mean * mean;
        float rinv = rsqrtf(var + 1e-5f);
        g_h[(size_t)p * DIM_ + d] = __float2half((tile[tx][ty + i * 8] - mean) * rinv * sc + sh);
    }
}

// ===================== q/k LN + RoPE, attention =====================
__global__ void k_qk(const float* __restrict__ qn_w, const float* __restrict__ qn_b,
                     const float* __restrict__ kn_w, const float* __restrict__ kn_b) {
    int gw = (blockIdx.x * blockDim.x + threadIdx.x) >> 5;
    int lane = threadIdx.x & 31;
    if (gw >= THW_ * HEADS_) return;
    int p = gw / HEADS_, head = gw % HEADS_;
    int t = p / HW_, hw = p % HW_;
    int hh = hw / RES_, ww = hw % RES_;
    float coord = (lane < 8) ? (float)t : (lane < 16) ? (float)hh : (float)ww;
    float inv = exp2f(-1.66096404744368f * (float)(lane & 7));   // 10000^(-j/8)
    float ang = coord * inv;
    float c = cosf(ang), s = sinf(ang);
    #pragma unroll
    for (int which = 0; which < 2; which++) {
        float* base = g_fused + (size_t)p * QKVN_ + which * 768 + head * DH_;
        float x1 = 0.f, x2 = 0.f;
        if (lane < 24) { x1 = base[2 * lane]; x2 = base[2 * lane + 1]; }
        float sum = x1 + x2, sq = x1 * x1 + x2 * x2;
        #pragma unroll
        for (int o = 16; o; o >>= 1) {
            sum += __shfl_xor_sync(0xffffffffu, sum, o);
            sq  += __shfl_xor_sync(0xffffffffu, sq, o);
        }
        float mean = sum * (1.f / 48.f);
        float var = sq * (1.f / 48.f) - mean * mean;
        float rinv = rsqrtf(var + 1e-5f);
        if (lane < 24) {
            const float* w = which ? kn_w : qn_w;
            const float* b = which ? kn_b : qn_b;
            float y1 = (x1 - mean) * rinv * w[2 * lane]     + b[2 * lane];
            float y2 = (x2 - mean) * rinv * w[2 * lane + 1] + b[2 * lane + 1];
            float o1 = y1 * c - y2 * s;
            float o2 = y1 * s + y2 * c;
            if (which == 0) { o1 *= 0.14433756729740643f; o2 *= 0.14433756729740643f; }
            base[2 * lane] = o1; base[2 * lane + 1] = o2;
        }
    }
}

__global__ void k_attn() {
    int warp = threadIdx.x >> 5, lane = threadIdx.x & 31;
    int gw = blockIdx.x * 8 + warp;
    if (gw >= THW_ * HEADS_) return;
    int head = gw % HEADS_, p = gw / HEADS_;
    int hw = p % HW_;
    int h = hw / RES_, w = hw % RES_;
    __shared__ float ssc[8][80];
    __shared__ int spk[8][80];
    float* sc = ssc[warp];
    int* pk = spk[warp];
    int h0 = min(max(h - 2, 0), RES_ - 5);
    int w0 = min(max(w - 2, 0), RES_ - 5);
    for (int j = lane; j < NBR_; j += 32) {
        int a = j / 25, r = j % 25, cc = r / 5, e = r % 5;
        pk[j] = (a * RES_ + h0 + cc) * RES_ + (w0 + e);
    }
    __syncwarp();
    const float* qp = g_fused + (size_t)p * QKVN_ + head * DH_;
    float qa = qp[lane];
    float qb = (lane < 16) ? qp[32 + lane] : 0.f;
    for (int j = 0; j < NBR_; j++) {
        const float* kp = g_fused + (size_t)pk[j] * QKVN_ + KOFF_ + head * DH_;
        float partial = qa * kp[lane];
        if (lane < 16) partial += qb * kp[32 + lane];
        #pragma unroll
        for (int o = 16; o; o >>= 1) partial += __shfl_xor_sync(0xffffffffu, partial, o);
        if (lane == 0) sc[j] = partial;
    }
    __syncwarp();
    float m = -1e30f;
    for (int j = lane; j < NBR_; j += 32) m = fmaxf(m, sc[j]);
    #pragma unroll
    for (int o = 16; o; o >>= 1) m = fmaxf(m, __shfl_xor_sync(0xffffffffu, m, o));
    float sum = 0.f;
    for (int j = lane; j < NBR_; j += 32) {
        float e = __expf(sc[j] - m);
        sc[j] = e; sum += e;
    }
    #pragma unroll
    for (int o = 16; o; o >>= 1) sum += __shfl_xor_sync(0xffffffffu, sum, o);
    float rs = 1.f / sum;
    for (int j = lane; j < NBR_; j += 32) sc[j] *= rs;
    __syncwarp();
    float acc_a = 0.f, acc_b = 0.f;
    for (int j = 0; j < NBR_; j++) {
        const float* vp = g_fused + (size_t)pk[j] * QKVN_ + VOFF_ + head * DH_;
        float pj = sc[j];
        acc_a += pj * vp[lane];
        if (lane < 16) acc_b += pj * vp[32 + lane];
    }
    g_afin[(size_t)p * KFIN_ + head * DH_ + lane] = __float2half(acc_a);
    if (lane < 16) g_afin[(size_t)p * KFIN_ + head * DH_ + 32 + lane] = __float2half(acc_b);
}

// ===================== launch =====================
extern "C" void kernel_launch(void* const* d_in, const int* in_sizes, int n_in,
                              void* d_out, int out_size) {
    const float* x       = (const float*)d_in[0];
    const float* emb     = (const float*)d_in[1];
    const float* w_mod   = (const float*)d_in[2];
    const float* b_mod   = (const float*)d_in[3];
    const float* qn_w    = (const float*)d_in[4];
    const float* qn_b    = (const float*)d_in[5];
    const float* kn_w    = (const float*)d_in[6];
    const float* kn_b    = (const float*)d_in[7];
    const float* W_fused = (const float*)d_in[8];
    const float* b_fused = (const float*)d_in[9];
    const float* W_out   = (const float*)d_in[10];
    const float* W_mlp   = (const float*)d_in[11];
    const float* b_mlp   = (const float*)d_in[12];
    float* out = (float*)d_out;

    __half* WF;    cudaGetSymbolAddress((void**)&WF, g_WF);
    __half* WFin;  cudaGetSymbolAddress((void**)&WFin, g_WFin);
    __half* gh;    cudaGetSymbolAddress((void**)&gh, g_h);
    float* gfused; cudaGetSymbolAddress((void**)&gfused, g_fused);
    __half* gafin; cudaGetSymbolAddress((void**)&gafin, g_afin);
    float* gstats; cudaGetSymbolAddress((void**)&gstats, g_stats);

    // smem: GEMM1 (MT=4): 2*(128*40 + 32*136)*2 = 37888 B
    //       GEMM2 (MT=2): max(2*(64*40 + 32*136)*2, 128*65*4) = 33280 B
    const int smem1 = 2 * (128 * ROWH + 32 * ROWB) * 2;
    const int smem2 = (2 * (64 * ROWH + 32 * ROWB) * 2 > 128 * 65 * 4)
                        ? 2 * (64 * ROWH + 32 * ROWB) * 2 : 128 * 65 * 4;

    cudaMemsetAsync(gstats, 0, 2 * THW_ * sizeof(float));
    k_cvtWF<<<(DIM_ * FUSEDN_ / 8 + 255) / 256, 256>>>(W_fused);
    k_cvtWFin<<<(KFIN_ * DIM_ / 8 + 255) / 256, 256>>>(W_out, W_mlp);
    k_mod<<<dim3(6, 3), 256>>>(emb, w_mod, b_mod);
    k_stats<<<dim3(8, 3), HW_>>>(x);
    k_applyT<<<dim3(HW_ / 32, DIM_ / 32, T_), dim3(32, 8)>>>(x);
    // fused GEMM: 1728 x 5376, K=768 (qkv fp32 + silu(mlp) half)
    k_gemm<4, 0><<<dim3(FUSEDN_ / 128, 14), 256, smem1>>>(
        gh, DIM_, WF, FUSEDN_, DIM_, b_fused, gfused, gafin, nullptr, nullptr);
    k_qk<<<(THW_ * HEADS_) / 8, 256>>>(qn_w, qn_b, kn_w, kn_b);
    k_attn<<<(THW_ * HEADS_) / 8, 256>>>();
    // final GEMM: 1728 x 768, K=3840, epilogue writes out (+bias+skip, transposed)
    k_gemm<2, 1><<<dim3(DIM_ / 128, 27), 256, smem2>>>(
        gafin, KFIN_, WFin, DIM_, KFIN_, b_mlp, nullptr, nullptr, out, x);
}

// round 10
// speedup vs baseline: 3.1769x; 1.0530x over previous
#include <cuda_runtime.h>
#include <cuda_fp16.h>
#include <math.h>
#include <stdint.h>

// ---- fixed problem shape (B=1) ----
#define T_      3
#define RES_    24
#define HW_     576
#define THW_    1728
#define DIM_    768
#define HEADS_  16
#define DH_     48
#define EMB_    1024
#define MLP_    3072
#define FUSEDN_ 5376
#define QKVN_   2304
#define QKN_    1536         // g_fused row: q|k fp32
#define VOFF_   1536
#define NBR_    75
#define KFIN_   3840         // 768 + 3072

// ---- scratch ----
__device__ __align__(16) float  g_mod[T_ * 2 * DIM_];
__device__ __align__(16) float  g_stats[2 * THW_];           // [sum | sumsq]
__device__ __align__(16) __half g_h[THW_ * DIM_];            // LN-mod activations
__device__ __align__(16) float  g_fused[THW_ * QKN_];        // q|k (fp32)
__device__ __align__(16) __half g_kvh[THW_ * 1536];          // [k(rope'd) | v] fp16
__device__ __align__(16) __half g_afin[THW_ * KFIN_];        // [xa | silu(mlp_h)]
__device__ __align__(16) __half g_WF[DIM_ * FUSEDN_];        // W_fused (half, [K][N])
__device__ __align__(16) __half g_WFin[KFIN_ * DIM_];        // [Wout;Wmlp] (half, [K][N])

__device__ __forceinline__ uint32_t smem_u32(const void* p) {
    uint32_t a;
    asm("{ .reg .u64 t; cvta.to.shared.u64 t, %1; cvt.u32.u64 %0, t; }" : "=r"(a) : "l"(p));
    return a;
}
__device__ __forceinline__ void cp16(uint32_t dst, const void* src, int srcsize) {
    asm volatile("cp.async.cg.shared.global [%0], [%1], 16, %2;"
                 :: "r"(dst), "l"(src), "r"(srcsize));
}
#define CP_COMMIT() asm volatile("cp.async.commit_group;" ::: "memory")
#define CP_WAIT0()  asm volatile("cp.async.wait_group 0;" ::: "memory")
#define CP_WAIT1()  asm volatile("cp.async.wait_group 1;" ::: "memory")

__device__ __forceinline__ void ldsm_x4(uint32_t& r0, uint32_t& r1, uint32_t& r2, uint32_t& r3,
                                        uint32_t addr) {
    asm volatile("ldmatrix.sync.aligned.m8n8.x4.shared.b16 {%0,%1,%2,%3}, [%4];"
                 : "=r"(r0), "=r"(r1), "=r"(r2), "=r"(r3) : "r"(addr));
}
__device__ __forceinline__ void ldsm_x4t(uint32_t& r0, uint32_t& r1, uint32_t& r2, uint32_t& r3,
                                         uint32_t addr) {
    asm volatile("ldmatrix.sync.aligned.m8n8.x4.trans.shared.b16 {%0,%1,%2,%3}, [%4];"
                 : "=r"(r0), "=r"(r1), "=r"(r2), "=r"(r3) : "r"(addr));
}
__device__ __forceinline__ void mma_f16(float* c, const uint32_t* a, const uint32_t* b) {
    asm volatile(
        "mma.sync.aligned.m16n8k16.row.col.f32.f16.f16.f32 "
        "{%0,%1,%2,%3}, {%4,%5,%6,%7}, {%8,%9}, {%0,%1,%2,%3};"
        : "+f"(c[0]), "+f"(c[1]), "+f"(c[2]), "+f"(c[3])
        : "r"(a[0]), "r"(a[1]), "r"(a[2]), "r"(a[3]), "r"(b[0]), "r"(b[1]));
}

#define ROWH 40    // A smem row: 32 halfs + 8 pad
#define ROWB 136   // B smem row: 128 halfs + 8 pad

// ===================== pipelined fp16 GEMM, B in [K][N] via ldmatrix.trans ======
// C = A[m][k] * B[k][n]. Tile (32*MT) x 128, K-chunk 32, cp.async double buffer.
// EPI 0: n<1536 -> g_fused fp32 (q|k); 1536<=n<2304 -> g_kvh half (v);
//        n>=2304 -> silu -> g_afin half. All +bias.
// EPI 1: smem-transpose epilogue -> out[t][n][hw] = acc + bias[n] + x[t][n][hw].
template<int MT, int EPI>
__global__ void __launch_bounds__(256, 2) k_gemm(
        const __half* __restrict__ A, int lda,
        const __half* __restrict__ B, int ldb, int Ktot,
        const float* __restrict__ bias,
        float* __restrict__ Cq, __half* __restrict__ kvh, __half* __restrict__ afin,
        float* __restrict__ outp, const float* __restrict__ x) {
    extern __shared__ __half smh[];
    const int AROWS = 32 * MT;
    const int ATILE = AROWS * ROWH;
    const int BTILE = 32 * ROWB;
    uint32_t s0 = smem_u32(smh);

    int tid = threadIdx.x;
    int wid = tid >> 5, lane = tid & 31;
    int wm = wid >> 2, wn = wid & 3;
    int lr = lane >> 2, lc = lane & 3;
    int m0 = blockIdx.y * AROWS, n0 = blockIdx.x * 128;

    float acc[MT][4][4];
    #pragma unroll
    for (int i = 0; i < MT; i++)
        #pragma unroll
        for (int j = 0; j < 4; j++)
            #pragma unroll
            for (int r = 0; r < 4; r++) acc[i][j][r] = 0.f;

    int nch = Ktot >> 5;

    auto issue = [&](int ch) {
        int buf = ch & 1;
        int k0 = ch << 5;
        uint32_t baseA = s0 + (uint32_t)(buf * ATILE) * 2u;
        uint32_t baseB = s0 + (uint32_t)((2 * ATILE) + buf * BTILE) * 2u;
        #pragma unroll
        for (int it = 0; it < MT / 2; it++) {     // A: AROWS x 32 (4 granules/row)
            int idx = it * 256 + tid;
            int row = idx >> 2, g = idx & 3;
            int m = m0 + row;
            const __half* pa = A + (size_t)(m < THW_ ? m : THW_ - 1) * lda + k0 + g * 8;
            cp16(baseA + (uint32_t)(row * ROWH + g * 8) * 2u, pa, (m < THW_) ? 16 : 0);
        }
        #pragma unroll
        for (int it = 0; it < 2; it++) {          // B: 32 rows x 128 (16 granules/row)
            int idx = it * 256 + tid;
            int row = idx >> 4, g = idx & 15;
            const __half* pb = B + (size_t)(k0 + row) * ldb + n0 + g * 8;
            cp16(baseB + (uint32_t)(row * ROWB + g * 8) * 2u, pb, 16);
        }
        CP_COMMIT();
    };

    issue(0);
    for (int ch = 0; ch < nch; ch++) {
        if (ch + 1 < nch) { issue(ch + 1); CP_WAIT1(); }
        else               CP_WAIT0();
        __syncthreads();
        int buf = ch & 1;
        uint32_t baseA = s0 + (uint32_t)(buf * ATILE) * 2u;
        uint32_t baseB = s0 + (uint32_t)((2 * ATILE) + buf * BTILE) * 2u;

        #pragma unroll
        for (int ks = 0; ks < 2; ks++) {
            uint32_t af[MT][4], bf[4][2];
            #pragma unroll
            for (int mt = 0; mt < MT; mt++) {     // A frags (non-trans, [m][k] smem)
                int r = wm * (16 * MT) + mt * 16 + (lane & 15);
                uint32_t addr = baseA + (uint32_t)(r * ROWH + ks * 16 + (lane >> 4) * 8) * 2u;
                ldsm_x4(af[mt][0], af[mt][1], af[mt][2], af[mt][3], addr);
            }
            #pragma unroll
            for (int np = 0; np < 2; np++) {      // B frags (trans, [k][n] smem)
                int q = lane >> 3;                // 0..3: (k-half, n-tile)
                int kr = ks * 16 + (q & 1) * 8 + (lane & 7);
                int nc = wn * 32 + (np * 2 + (q >> 1)) * 8;
                uint32_t addr = baseB + (uint32_t)(kr * ROWB + nc) * 2u;
                ldsm_x4t(bf[np * 2][0], bf[np * 2][1], bf[np * 2 + 1][0], bf[np * 2 + 1][1], addr);
            }
            #pragma unroll
            for (int mt = 0; mt < MT; mt++)
                #pragma unroll
                for (int nt = 0; nt < 4; nt++)
                    mma_f16(acc[mt][nt], af[mt], bf[nt]);
        }
        __syncthreads();
    }

    if (EPI == 0) {
        int kind = (n0 >= QKVN_) ? 2 : (n0 >= VOFF_) ? 1 : 0;   // uniform per block
        #pragma unroll
        for (int mt = 0; mt < MT; mt++) {
            #pragma unroll
            for (int hf = 0; hf < 2; hf++) {
                int mrow = m0 + wm * (16 * MT) + mt * 16 + lr + hf * 8;
                if (mrow >= THW_) continue;
                #pragma unroll
                for (int nt = 0; nt < 4; nt++) {
                    int n = n0 + wn * 32 + nt * 8 + 2 * lc;
                    float v0 = acc[mt][nt][hf * 2 + 0] + bias[n];
                    float v1 = acc[mt][nt][hf * 2 + 1] + bias[n + 1];
                    if (kind == 2) {                    // silu(mlp) -> half
                        v0 = v0 / (1.f + expf(-v0));
                        v1 = v1 / (1.f + expf(-v1));
                        *(__half2*)(afin + (size_t)mrow * KFIN_ + 768 + (n - QKVN_)) =
                            __floats2half2_rn(v0, v1);
                    } else if (kind == 1) {             // v -> half
                        *(__half2*)(kvh + (size_t)mrow * 1536 + 768 + (n - VOFF_)) =
                            __floats2half2_rn(v0, v1);
                    } else {                            // q|k -> fp32
                        *(float2*)(Cq + (size_t)mrow * QKN_ + n) = make_float2(v0, v1);
                    }
                }
            }
        }
    } else {
        // stage 64x128 tile in smem as [n][m], then write coalesced along hw
        float* st = (float*)smh;
        #pragma unroll
        for (int mt = 0; mt < MT; mt++) {
            #pragma unroll
            for (int hf = 0; hf < 2; hf++) {
                int ml = wm * (16 * MT) + mt * 16 + lr + hf * 8;
                #pragma unroll
                for (int nt = 0; nt < 4; nt++) {
                    int nl = wn * 32 + nt * 8 + 2 * lc;
                    st[nl * 65 + ml]       = acc[mt][nt][hf * 2 + 0];
                    st[(nl + 1) * 65 + ml] = acc[mt][nt][hf * 2 + 1];
                }
            }
        }
        __syncthreads();
        int t = m0 / HW_, hw0 = m0 % HW_;
        int nr = tid >> 1, mh = (tid & 1) * 32;
        int n = n0 + nr;
        float bb = bias[n];
        const float* xrow = x + ((size_t)t * DIM_ + n) * HW_ + hw0 + mh;
        float* orow = outp + ((size_t)t * DIM_ + n) * HW_ + hw0 + mh;
        #pragma unroll
        for (int i = 0; i < 8; i++) {
            float4 xs = *(const float4*)(xrow + i * 4);
            float4 o;
            o.x = st[nr * 65 + mh + i * 4 + 0] + bb + xs.x;
            o.y = st[nr * 65 + mh + i * 4 + 1] + bb + xs.y;
            o.z = st[nr * 65 + mh + i * 4 + 2] + bb + xs.z;
            o.w = st[nr * 65 + mh + i * 4 + 3] + bb + xs.w;
            *(float4*)(orow + i * 4) = o;
        }
    }
}

// ===================== weight converts (fp32 -> half, layout preserved) ========
__global__ void k_cvtWF(const float* __restrict__ W) {      // [768][5376]
    int i = blockIdx.x * 256 + threadIdx.x;
    if (i < DIM_ * FUSEDN_ / 8) {
        float4 a = *(const float4*)(W + (size_t)i * 8);
        float4 b = *(const float4*)(W + (size_t)i * 8 + 4);
        __half2 h[4] = { __floats2half2_rn(a.x, a.y), __floats2half2_rn(a.z, a.w),
                         __floats2half2_rn(b.x, b.y), __floats2half2_rn(b.z, b.w) };
        *(uint2*)(g_WF + (size_t)i * 8)     = *(uint2*)&h[0];
        *(uint2*)(g_WF + (size_t)i * 8 + 4) = *(uint2*)&h[2];
    }
}
__global__ void k_cvtWFin(const float* __restrict__ Wout, const float* __restrict__ Wmlp) {
    int i = blockIdx.x * 256 + threadIdx.x;
    const int N1 = DIM_ * DIM_ / 8;
    if (i < KFIN_ * DIM_ / 8) {
        const float* src = (i < N1) ? (Wout + (size_t)i * 8)
                                    : (Wmlp + (size_t)(i - N1) * 8);
        float4 a = *(const float4*)(src);
        float4 b = *(const float4*)(src + 4);
        __half2 h[4] = { __floats2half2_rn(a.x, a.y), __floats2half2_rn(a.z, a.w),
                         __floats2half2_rn(b.x, b.y), __floats2half2_rn(b.z, b.w) };
        *(uint2*)(g_WFin + (size_t)i * 8)     = *(uint2*)&h[0];
        *(uint2*)(g_WFin + (size_t)i * 8 + 4) = *(uint2*)&h[2];
    }
}

// ===================== modulation / LN =====================
__global__ void k_mod(const float* __restrict__ emb, const float* __restrict__ w_mod,
                      const float* __restrict__ b_mod) {
    int t = blockIdx.y, col = blockIdx.x * 256 + threadIdx.x;
    __shared__ float se[EMB_];
    for (int k = threadIdx.x; k < EMB_; k += 256) {
        float e = emb[t * EMB_ + k];
        se[k] = e / (1.f + expf(-e));
    }
    __syncthreads();
    float acc = 0.f;
    #pragma unroll 8
    for (int k = 0; k < EMB_; k++) acc += se[k] * w_mod[k * (2 * DIM_) + col];
    g_mod[t * (2 * DIM_) + col] = acc + b_mod[col];
}

__global__ void k_stats(const float* __restrict__ x) {      // coalesced LN stats
    int t = blockIdx.y, d0 = blockIdx.x * 16;
    int hw = threadIdx.x;
    float s = 0.f, q = 0.f;
    const float* xp = x + ((size_t)t * DIM_ + d0) * HW_ + hw;
    #pragma unroll
    for (int i = 0; i < 16; i++) {
        float v = xp[(size_t)i * HW_];
        s += v; q += v * v;
    }
    atomicAdd(&g_stats[t * HW_ + hw], s);
    atomicAdd(&g_stats[THW_ + t * HW_ + hw], q);
}

__global__ void k_applyT(const float* __restrict__ x) {     // transpose + LN + mod
    __shared__ float tile[32][33];
    int t = blockIdx.z;
    int hw0 = blockIdx.x * 32, d0 = blockIdx.y * 32;
    int tx = threadIdx.x, ty = threadIdx.y;
    #pragma unroll
    for (int i = 0; i < 4; i++)
        tile[ty + i * 8][tx] = x[((size_t)t * DIM_ + d0 + ty + i * 8) * HW_ + hw0 + tx];
    __syncthreads();
    int d = d0 + tx;
    float sc = 1.f + g_mod[t * 1536 + d];
    float sh = g_mod[t * 1536 + 768 + d];
    #pragma unroll
    for (int i = 0; i < 4; i++) {
        int hw = hw0 + ty + i * 8;
        int p = t * HW_ + hw;
        float sum = g_stats[p], sq = g_stats[THW_ + p];
        float mean = sum * (1.f / 768.f);
        float var = sq * (1.f / 768.f) - mean * mean;
        float rinv = rsqrtf(var + 1e-5f);
        g_h[(size_t)p * DIM_ + d] = __float2half((tile[tx][ty + i * 8] - mean) * rinv * sc + sh);
    }
}

// ===================== q/k LN + RoPE (k -> half), attention =====================
__global__ void k_qk(const float* __restrict__ qn_w, const float* __restrict__ qn_b,
                     const float* __restrict__ kn_w, const float* __restrict__ kn_b) {
    int gw = (blockIdx.x * blockDim.x + threadIdx.x) >> 5;
    int lane = threadIdx.x & 31;
    if (gw >= THW_ * HEADS_) return;
    int p = gw / HEADS_, head = gw % HEADS_;
    int t = p / HW_, hw = p % HW_;
    int hh = hw / RES_, ww = hw % RES_;
    float coord = (lane < 8) ? (float)t : (lane < 16) ? (float)hh : (float)ww;
    float inv = exp2f(-1.66096404744368f * (float)(lane & 7));   // 10000^(-j/8)
    float ang = coord * inv;
    float c = cosf(ang), s = sinf(ang);
    #pragma unroll
    for (int which = 0; which < 2; which++) {
        float* base = g_fused + (size_t)p * QKN_ + which * 768 + head * DH_;
        float x1 = 0.f, x2 = 0.f;
        if (lane < 24) { x1 = base[2 * lane]; x2 = base[2 * lane + 1]; }
        float sum = x1 + x2, sq = x1 * x1 + x2 * x2;
        #pragma unroll
        for (int o = 16; o; o >>= 1) {
            sum += __shfl_xor_sync(0xffffffffu, sum, o);
            sq  += __shfl_xor_sync(0xffffffffu, sq, o);
        }
        float mean = sum * (1.f / 48.f);
        float var = sq * (1.f / 48.f) - mean * mean;
        float rinv = rsqrtf(var + 1e-5f);
        if (lane < 24) {
            const float* w = which ? kn_w : qn_w;
            const float* b = which ? kn_b : qn_b;
            float y1 = (x1 - mean) * rinv * w[2 * lane]     + b[2 * lane];
            float y2 = (x2 - mean) * rinv * w[2 * lane + 1] + b[2 * lane + 1];
            float o1 = y1 * c - y2 * s;
            float o2 = y1 * s + y2 * c;
            if (which == 0) {
                o1 *= 0.14433756729740643f; o2 *= 0.14433756729740643f;
                base[2 * lane] = o1; base[2 * lane + 1] = o2;        // q stays fp32
            } else {
                *(__half2*)(g_kvh + (size_t)p * 1536 + head * DH_ + 2 * lane) =
                    __floats2half2_rn(o1, o2);                        // k -> half
            }
        }
    }
}

__global__ void k_attn() {
    int warp = threadIdx.x >> 5, lane = threadIdx.x & 31;
    int gw = blockIdx.x * 8 + warp;
    if (gw >= THW_ * HEADS_) return;
    int head = gw % HEADS_, p = gw / HEADS_;
    int hw = p % HW_;
    int h = hw / RES_, w = hw % RES_;
    __shared__ float ssc[8][80];
    __shared__ int spk[8][80];
    float* sc = ssc[warp];
    int* pk = spk[warp];
    int h0 = min(max(h - 2, 0), RES_ - 5);
    int w0 = min(max(w - 2, 0), RES_ - 5);
    for (int j = lane; j < NBR_; j += 32) {
        int a = j / 25, r = j % 25, cc = r / 5, e = r % 5;
        pk[j] = (a * RES_ + h0 + cc) * RES_ + (w0 + e);
    }
    __syncwarp();
    float qa = 0.f, qb = 0.f;
    if (lane < 24) {
        float2 qv = *(const float2*)(g_fused + (size_t)p * QKN_ + head * DH_ + 2 * lane);
        qa = qv.x; qb = qv.y;
    }
    #pragma unroll 5
    for (int j = 0; j < NBR_; j++) {
        float partial = 0.f;
        if (lane < 24) {
            __half2 kv = *(const __half2*)(g_kvh + (size_t)pk[j] * 1536 + head * DH_ + 2 * lane);
            float2 kf = __half22float2(kv);
            partial = qa * kf.x + qb * kf.y;
        }
        #pragma unroll
        for (int o = 16; o; o >>= 1) partial += __shfl_xor_sync(0xffffffffu, partial, o);
        if (lane == 0) sc[j] = partial;
    }
    __syncwarp();
    float m = -1e30f;
    for (int j = lane; j < NBR_; j += 32) m = fmaxf(m, sc[j]);
    #pragma unroll
    for (int o = 16; o; o >>= 1) m = fmaxf(m, __shfl_xor_sync(0xffffffffu, m, o));
    float sum = 0.f;
    for (int j = lane; j < NBR_; j += 32) {
        float e = __expf(sc[j] - m);
        sc[j] = e; sum += e;
    }
    #pragma unroll
    for (int o = 16; o; o >>= 1) sum += __shfl_xor_sync(0xffffffffu, sum, o);
    float rs = 1.f / sum;
    for (int j = lane; j < NBR_; j += 32) sc[j] *= rs;
    __syncwarp();
    float acc_a = 0.f, acc_b = 0.f;
    if (lane < 24) {
        #pragma unroll 5
        for (int j = 0; j < NBR_; j++) {
            __half2 vv = *(const __half2*)(g_kvh + (size_t)pk[j] * 1536 + 768 + head * DH_ + 2 * lane);
            float2 vf = __half22float2(vv);
            float pj = sc[j];
            acc_a += pj * vf.x;
            acc_b += pj * vf.y;
        }
        *(__half2*)(g_afin + (size_t)p * KFIN_ + head * DH_ + 2 * lane) =
            __floats2half2_rn(acc_a, acc_b);
    }
}

// ===================== launch =====================
extern "C" void kernel_launch(void* const* d_in, const int* in_sizes, int n_in,
                              void* d_out, int out_size) {
    const float* x       = (const float*)d_in[0];
    const float* emb     = (const float*)d_in[1];
    const float* w_mod   = (const float*)d_in[2];
    const float* b_mod   = (const float*)d_in[3];
    const float* qn_w    = (const float*)d_in[4];
    const float* qn_b    = (const float*)d_in[5];
    const float* kn_w    = (const float*)d_in[6];
    const float* kn_b    = (const float*)d_in[7];
    const float* W_fused = (const float*)d_in[8];
    const float* b_fused = (const float*)d_in[9];
    const float* W_out   = (const float*)d_in[10];
    const float* W_mlp   = (const float*)d_in[11];
    const float* b_mlp   = (const float*)d_in[12];
    float* out = (float*)d_out;

    __half* WF;    cudaGetSymbolAddress((void**)&WF, g_WF);
    __half* WFin;  cudaGetSymbolAddress((void**)&WFin, g_WFin);
    __half* gh;    cudaGetSymbolAddress((void**)&gh, g_h);
    float* gfused; cudaGetSymbolAddress((void**)&gfused, g_fused);
    __half* gkvh;  cudaGetSymbolAddress((void**)&gkvh, g_kvh);
    __half* gafin; cudaGetSymbolAddress((void**)&gafin, g_afin);
    float* gstats; cudaGetSymbolAddress((void**)&gstats, g_stats);

    const int smem1 = 2 * (128 * ROWH + 32 * ROWB) * 2;
    const int smem2 = (2 * (64 * ROWH + 32 * ROWB) * 2 > 128 * 65 * 4)
                        ? 2 * (64 * ROWH + 32 * ROWB) * 2 : 128 * 65 * 4;

    cudaMemsetAsync(gstats, 0, 2 * THW_ * sizeof(float));
    k_cvtWF<<<(DIM_ * FUSEDN_ / 8 + 255) / 256, 256>>>(W_fused);
    k_cvtWFin<<<(KFIN_ * DIM_ / 8 + 255) / 256, 256>>>(W_out, W_mlp);
    k_mod<<<dim3(6, 3), 256>>>(emb, w_mod, b_mod);
    k_stats<<<dim3(48, 3), HW_>>>(x);
    k_applyT<<<dim3(HW_ / 32, DIM_ / 32, T_), dim3(32, 8)>>>(x);
    // fused GEMM: 1728 x 5376, K=768 (q|k fp32, v half, silu(mlp) half)
    k_gemm<4, 0><<<dim3(FUSEDN_ / 128, 14), 256, smem1>>>(
        gh, DIM_, WF, FUSEDN_, DIM_, b_fused, gfused, gkvh, gafin, nullptr, nullptr);
    k_qk<<<(THW_ * HEADS_) / 8, 256>>>(qn_w, qn_b, kn_w, kn_b);
    k_attn<<<(THW_ * HEADS_) / 8, 256>>>();
    // final GEMM: 1728 x 768, K=3840, epilogue writes out (+bias+skip, transposed)
    k_gemm<2, 1><<<dim3(DIM_ / 128, 27), 256, smem2>>>(
        gafin, KFIN_, WFin, DIM_, KFIN_, b_mlp, nullptr, nullptr, nullptr, out, x);
}

// round 11
// speedup vs baseline: 3.7172x; 1.1700x over previous
#include <cuda_runtime.h>
#include <cuda_fp16.h>
#include <math.h>
#include <stdint.h>

// ---- fixed problem shape (B=1) ----
#define T_      3
#define RES_    24
#define HW_     576
#define THW_    1728
#define DIM_    768
#define HEADS_  16
#define DH_     48
#define EMB_    1024
#define MLP_    3072
#define FUSEDN_ 5376
#define QKVN_   2304
#define QKN_    1536         // g_fused row: q|k fp32
#define VOFF_   1536
#define NBR_    75
#define KFIN_   3840         // 768 + 3072

// ---- scratch ----
__device__ __align__(16) float  g_mod[T_ * 2 * DIM_];
__device__ __align__(16) float  g_stats[2 * THW_];           // [sum | sumsq]
__device__ __align__(16) __half g_h[THW_ * DIM_];            // LN-mod activations
__device__ __align__(16) float  g_fused[THW_ * QKN_];        // q|k (fp32)
__device__ __align__(16) __half g_kvh[THW_ * 1536];          // [k(rope'd) | v] fp16
__device__ __align__(16) __half g_afin[THW_ * KFIN_];        // [xa | silu(mlp_h)]
__device__ __align__(16) __half g_WF[DIM_ * FUSEDN_];        // W_fused (half, [K][N])
__device__ __align__(16) __half g_WFin[KFIN_ * DIM_];        // [Wout;Wmlp] (half, [K][N])

__device__ __forceinline__ uint32_t smem_u32(const void* p) {
    uint32_t a;
    asm("{ .reg .u64 t; cvta.to.shared.u64 t, %1; cvt.u32.u64 %0, t; }" : "=r"(a) : "l"(p));
    return a;
}
__device__ __forceinline__ void cp16(uint32_t dst, const void* src, int srcsize) {
    asm volatile("cp.async.cg.shared.global [%0], [%1], 16, %2;"
                 :: "r"(dst), "l"(src), "r"(srcsize));
}
#define CP_COMMIT() asm volatile("cp.async.commit_group;" ::: "memory")
#define CP_WAIT0()  asm volatile("cp.async.wait_group 0;" ::: "memory")
#define CP_WAIT1()  asm volatile("cp.async.wait_group 1;" ::: "memory")

__device__ __forceinline__ void ldsm_x4(uint32_t& r0, uint32_t& r1, uint32_t& r2, uint32_t& r3,
                                        uint32_t addr) {
    asm volatile("ldmatrix.sync.aligned.m8n8.x4.shared.b16 {%0,%1,%2,%3}, [%4];"
                 : "=r"(r0), "=r"(r1), "=r"(r2), "=r"(r3) : "r"(addr));
}
__device__ __forceinline__ void ldsm_x4t(uint32_t& r0, uint32_t& r1, uint32_t& r2, uint32_t& r3,
                                         uint32_t addr) {
    asm volatile("ldmatrix.sync.aligned.m8n8.x4.trans.shared.b16 {%0,%1,%2,%3}, [%4];"
                 : "=r"(r0), "=r"(r1), "=r"(r2), "=r"(r3) : "r"(addr));
}
__device__ __forceinline__ void mma_f16(float* c, const uint32_t* a, const uint32_t* b) {
    asm volatile(
        "mma.sync.aligned.m16n8k16.row.col.f32.f16.f16.f32 "
        "{%0,%1,%2,%3}, {%4,%5,%6,%7}, {%8,%9}, {%0,%1,%2,%3};"
        : "+f"(c[0]), "+f"(c[1]), "+f"(c[2]), "+f"(c[3])
        : "r"(a[0]), "r"(a[1]), "r"(a[2]), "r"(a[3]), "r"(b[0]), "r"(b[1]));
}

#define ROWH 40    // A smem row: 32 halfs + 8 pad
#define ROWB 136   // B smem row: 128 halfs + 8 pad

// ===================== pipelined fp16 GEMM, B in [K][N] via ldmatrix.trans ======
template<int MT, int EPI>
__global__ void __launch_bounds__(256, 2) k_gemm(
        const __half* __restrict__ A, int lda,
        const __half* __restrict__ B, int ldb, int Ktot,
        const float* __restrict__ bias,
        float* __restrict__ Cq, __half* __restrict__ kvh, __half* __restrict__ afin,
        float* __restrict__ outp, const float* __restrict__ x) {
    extern __shared__ __half smh[];
    const int AROWS = 32 * MT;
    const int ATILE = AROWS * ROWH;
    const int BTILE = 32 * ROWB;
    uint32_t s0 = smem_u32(smh);

    int tid = threadIdx.x;
    int wid = tid >> 5, lane = tid & 31;
    int wm = wid >> 2, wn = wid & 3;
    int lr = lane >> 2, lc = lane & 3;
    int m0 = blockIdx.y * AROWS, n0 = blockIdx.x * 128;

    float acc[MT][4][4];
    #pragma unroll
    for (int i = 0; i < MT; i++)
        #pragma unroll
        for (int j = 0; j < 4; j++)
            #pragma unroll
            for (int r = 0; r < 4; r++) acc[i][j][r] = 0.f;

    int nch = Ktot >> 5;

    auto issue = [&](int ch) {
        int buf = ch & 1;
        int k0 = ch << 5;
        uint32_t baseA = s0 + (uint32_t)(buf * ATILE) * 2u;
        uint32_t baseB = s0 + (uint32_t)((2 * ATILE) + buf * BTILE) * 2u;
        #pragma unroll
        for (int it = 0; it < MT / 2; it++) {
            int idx = it * 256 + tid;
            int row = idx >> 2, g = idx & 3;
            int m = m0 + row;
            const __half* pa = A + (size_t)(m < THW_ ? m : THW_ - 1) * lda + k0 + g * 8;
            cp16(baseA + (uint32_t)(row * ROWH + g * 8) * 2u, pa, (m < THW_) ? 16 : 0);
        }
        #pragma unroll
        for (int it = 0; it < 2; it++) {
            int idx = it * 256 + tid;
            int row = idx >> 4, g = idx & 15;
            const __half* pb = B + (size_t)(k0 + row) * ldb + n0 + g * 8;
            cp16(baseB + (uint32_t)(row * ROWB + g * 8) * 2u, pb, 16);
        }
        CP_COMMIT();
    };

    issue(0);
    for (int ch = 0; ch < nch; ch++) {
        if (ch + 1 < nch) { issue(ch + 1); CP_WAIT1(); }
        else               CP_WAIT0();
        __syncthreads();
        int buf = ch & 1;
        uint32_t baseA = s0 + (uint32_t)(buf * ATILE) * 2u;
        uint32_t baseB = s0 + (uint32_t)((2 * ATILE) + buf * BTILE) * 2u;

        #pragma unroll
        for (int ks = 0; ks < 2; ks++) {
            uint32_t af[MT][4], bf[4][2];
            #pragma unroll
            for (int mt = 0; mt < MT; mt++) {
                int r = wm * (16 * MT) + mt * 16 + (lane & 15);
                uint32_t addr = baseA + (uint32_t)(r * ROWH + ks * 16 + (lane >> 4) * 8) * 2u;
                ldsm_x4(af[mt][0], af[mt][1], af[mt][2], af[mt][3], addr);
            }
            #pragma unroll
            for (int np = 0; np < 2; np++) {
                int q = lane >> 3;
                int kr = ks * 16 + (q & 1) * 8 + (lane & 7);
                int nc = wn * 32 + (np * 2 + (q >> 1)) * 8;
                uint32_t addr = baseB + (uint32_t)(kr * ROWB + nc) * 2u;
                ldsm_x4t(bf[np * 2][0], bf[np * 2][1], bf[np * 2 + 1][0], bf[np * 2 + 1][1], addr);
            }
            #pragma unroll
            for (int mt = 0; mt < MT; mt++)
                #pragma unroll
                for (int nt = 0; nt < 4; nt++)
                    mma_f16(acc[mt][nt], af[mt], bf[nt]);
        }
        __syncthreads();
    }

    if (EPI == 0) {
        int kind = (n0 >= QKVN_) ? 2 : (n0 >= VOFF_) ? 1 : 0;
        #pragma unroll
        for (int mt = 0; mt < MT; mt++) {
            #pragma unroll
            for (int hf = 0; hf < 2; hf++) {
                int mrow = m0 + wm * (16 * MT) + mt * 16 + lr + hf * 8;
                if (mrow >= THW_) continue;
                #pragma unroll
                for (int nt = 0; nt < 4; nt++) {
                    int n = n0 + wn * 32 + nt * 8 + 2 * lc;
                    float v0 = acc[mt][nt][hf * 2 + 0] + bias[n];
                    float v1 = acc[mt][nt][hf * 2 + 1] + bias[n + 1];
                    if (kind == 2) {
                        v0 = v0 / (1.f + expf(-v0));
                        v1 = v1 / (1.f + expf(-v1));
                        *(__half2*)(afin + (size_t)mrow * KFIN_ + 768 + (n - QKVN_)) =
                            __floats2half2_rn(v0, v1);
                    } else if (kind == 1) {
                        *(__half2*)(kvh + (size_t)mrow * 1536 + 768 + (n - VOFF_)) =
                            __floats2half2_rn(v0, v1);
                    } else {
                        *(float2*)(Cq + (size_t)mrow * QKN_ + n) = make_float2(v0, v1);
                    }
                }
            }
        }
    } else {
        float* st = (float*)smh;
        #pragma unroll
        for (int mt = 0; mt < MT; mt++) {
            #pragma unroll
            for (int hf = 0; hf < 2; hf++) {
                int ml = wm * (16 * MT) + mt * 16 + lr + hf * 8;
                #pragma unroll
                for (int nt = 0; nt < 4; nt++) {
                    int nl = wn * 32 + nt * 8 + 2 * lc;
                    st[nl * 65 + ml]       = acc[mt][nt][hf * 2 + 0];
                    st[(nl + 1) * 65 + ml] = acc[mt][nt][hf * 2 + 1];
                }
            }
        }
        __syncthreads();
        int t = m0 / HW_, hw0 = m0 % HW_;
        int nr = tid >> 1, mh = (tid & 1) * 32;
        int n = n0 + nr;
        float bb = bias[n];
        const float* xrow = x + ((size_t)t * DIM_ + n) * HW_ + hw0 + mh;
        float* orow = outp + ((size_t)t * DIM_ + n) * HW_ + hw0 + mh;
        #pragma unroll
        for (int i = 0; i < 8; i++) {
            float4 xs = *(const float4*)(xrow + i * 4);
            float4 o;
            o.x = st[nr * 65 + mh + i * 4 + 0] + bb + xs.x;
            o.y = st[nr * 65 + mh + i * 4 + 1] + bb + xs.y;
            o.z = st[nr * 65 + mh + i * 4 + 2] + bb + xs.z;
            o.w = st[nr * 65 + mh + i * 4 + 3] + bb + xs.w;
            *(float4*)(orow + i * 4) = o;
        }
    }
}

// ===================== weight converts =====================
__global__ void k_cvtWF(const float* __restrict__ W) {
    int i = blockIdx.x * 256 + threadIdx.x;
    if (i < DIM_ * FUSEDN_ / 8) {
        float4 a = *(const float4*)(W + (size_t)i * 8);
        float4 b = *(const float4*)(W + (size_t)i * 8 + 4);
        __half2 h[4] = { __floats2half2_rn(a.x, a.y), __floats2half2_rn(a.z, a.w),
                         __floats2half2_rn(b.x, b.y), __floats2half2_rn(b.z, b.w) };
        *(uint2*)(g_WF + (size_t)i * 8)     = *(uint2*)&h[0];
        *(uint2*)(g_WF + (size_t)i * 8 + 4) = *(uint2*)&h[2];
    }
}
__global__ void k_cvtWFin(const float* __restrict__ Wout, const float* __restrict__ Wmlp) {
    int i = blockIdx.x * 256 + threadIdx.x;
    const int N1 = DIM_ * DIM_ / 8;
    if (i < KFIN_ * DIM_ / 8) {
        const float* src = (i < N1) ? (Wout + (size_t)i * 8)
                                    : (Wmlp + (size_t)(i - N1) * 8);
        float4 a = *(const float4*)(src);
        float4 b = *(const float4*)(src + 4);
        __half2 h[4] = { __floats2half2_rn(a.x, a.y), __floats2half2_rn(a.z, a.w),
                         __floats2half2_rn(b.x, b.y), __floats2half2_rn(b.z, b.w) };
        *(uint2*)(g_WFin + (size_t)i * 8)     = *(uint2*)&h[0];
        *(uint2*)(g_WFin + (size_t)i * 8 + 4) = *(uint2*)&h[2];
    }
}

// ===================== modulation / LN =====================
__global__ void k_mod(const float* __restrict__ emb, const float* __restrict__ w_mod,
                      const float* __restrict__ b_mod) {
    int t = blockIdx.y, col = blockIdx.x * 256 + threadIdx.x;
    __shared__ float se[EMB_];
    for (int k = threadIdx.x; k < EMB_; k += 256) {
        float e = emb[t * EMB_ + k];
        se[k] = e / (1.f + expf(-e));
    }
    __syncthreads();
    float acc = 0.f;
    #pragma unroll 8
    for (int k = 0; k < EMB_; k++) acc += se[k] * w_mod[k * (2 * DIM_) + col];
    g_mod[t * (2 * DIM_) + col] = acc + b_mod[col];
}

__global__ void k_stats(const float* __restrict__ x) {
    int t = blockIdx.y, d0 = blockIdx.x * 8;
    int hw = threadIdx.x;
    float s = 0.f, q = 0.f;
    const float* xp = x + ((size_t)t * DIM_ + d0) * HW_ + hw;
    #pragma unroll
    for (int i = 0; i < 8; i++) {
        float v = xp[(size_t)i * HW_];
        s += v; q += v * v;
    }
    atomicAdd(&g_stats[t * HW_ + hw], s);
    atomicAdd(&g_stats[THW_ + t * HW_ + hw], q);
}

__global__ void k_applyT(const float* __restrict__ x) {
    __shared__ float tile[32][33];
    int t = blockIdx.z;
    int hw0 = blockIdx.x * 32, d0 = blockIdx.y * 32;
    int tx = threadIdx.x, ty = threadIdx.y;
    #pragma unroll
    for (int i = 0; i < 4; i++)
        tile[ty + i * 8][tx] = x[((size_t)t * DIM_ + d0 + ty + i * 8) * HW_ + hw0 + tx];
    __syncthreads();
    int d = d0 + tx;
    float sc = 1.f + g_mod[t * 1536 + d];
    float sh = g_mod[t * 1536 + 768 + d];
    #pragma unroll
    for (int i = 0; i < 4; i++) {
        int hw = hw0 + ty + i * 8;
        int p = t * HW_ + hw;
        float sum = g_stats[p], sq = g_stats[THW_ + p];
        float mean = sum * (1.f / 768.f);
        float var = sq * (1.f / 768.f) - mean * mean;
        float rinv = rsqrtf(var + 1e-5f);
        g_h[(size_t)p * DIM_ + d] = __float2half((tile[tx][ty + i * 8] - mean) * rinv * sc + sh);
    }
}

// ===================== q/k LN + RoPE (k -> half) =====================
__global__ void k_qk(const float* __restrict__ qn_w, const float* __restrict__ qn_b,
                     const float* __restrict__ kn_w, const float* __restrict__ kn_b) {
    int gw = (blockIdx.x * blockDim.x + threadIdx.x) >> 5;
    int lane = threadIdx.x & 31;
    if (gw >= THW_ * HEADS_) return;
    int p = gw / HEADS_, head = gw % HEADS_;
    int t = p / HW_, hw = p % HW_;
    int hh = hw / RES_, ww = hw % RES_;
    float coord = (lane < 8) ? (float)t : (lane < 16) ? (float)hh : (float)ww;
    float inv = exp2f(-1.66096404744368f * (float)(lane & 7));
    float ang = coord * inv;
    float c = cosf(ang), s = sinf(ang);
    #pragma unroll
    for (int which = 0; which < 2; which++) {
        float* base = g_fused + (size_t)p * QKN_ + which * 768 + head * DH_;
        float x1 = 0.f, x2 = 0.f;
        if (lane < 24) { x1 = base[2 * lane]; x2 = base[2 * lane + 1]; }
        float sum = x1 + x2, sq = x1 * x1 + x2 * x2;
        #pragma unroll
        for (int o = 16; o; o >>= 1) {
            sum += __shfl_xor_sync(0xffffffffu, sum, o);
            sq  += __shfl_xor_sync(0xffffffffu, sq, o);
        }
        float mean = sum * (1.f / 48.f);
        float var = sq * (1.f / 48.f) - mean * mean;
        float rinv = rsqrtf(var + 1e-5f);
        if (lane < 24) {
            const float* w = which ? kn_w : qn_w;
            const float* b = which ? kn_b : qn_b;
            float y1 = (x1 - mean) * rinv * w[2 * lane]     + b[2 * lane];
            float y2 = (x2 - mean) * rinv * w[2 * lane + 1] + b[2 * lane + 1];
            float o1 = y1 * c - y2 * s;
            float o2 = y1 * s + y2 * c;
            if (which == 0) {
                o1 *= 0.14433756729740643f; o2 *= 0.14433756729740643f;
                base[2 * lane] = o1; base[2 * lane + 1] = o2;
            } else {
                *(__half2*)(g_kvh + (size_t)p * 1536 + head * DH_ + 2 * lane) =
                    __floats2half2_rn(o1, o2);
            }
        }
    }
}

// ===================== attention: 4 neighbor-groups of 8 lanes =====================
__global__ void k_attn() {
    int warp = threadIdx.x >> 5, lane = threadIdx.x & 31;
    int gw = blockIdx.x * 8 + warp;
    if (gw >= THW_ * HEADS_) return;
    int head = gw % HEADS_, p = gw / HEADS_;
    int hw = p % HW_;
    int h = hw / RES_, w = hw % RES_;
    int grp = lane >> 3, gl = lane & 7;         // group 0..3, lane-in-group 0..7

    __shared__ float ssc[8][80];
    __shared__ int spk[8][80];
    float* sc = ssc[warp];
    int* pk = spk[warp];
    int h0 = min(max(h - 2, 0), RES_ - 5);
    int w0 = min(max(w - 2, 0), RES_ - 5);
    for (int j = lane; j < NBR_; j += 32) {
        int a = j / 25, r = j % 25, cc = r / 5, e = r % 5;
        pk[j] = (a * RES_ + h0 + cc) * RES_ + (w0 + e);
    }
    __syncwarp();

    // q dims [gl*8, gl*8+8) in fp32 (lanes gl<6 active per group)
    float qr[8];
    if (gl < 6) {
        float4 qv0 = *(const float4*)(g_fused + (size_t)p * QKN_ + head * DH_ + gl * 8);
        float4 qv1 = *(const float4*)(g_fused + (size_t)p * QKN_ + head * DH_ + gl * 8 + 4);
        qr[0] = qv0.x; qr[1] = qv0.y; qr[2] = qv0.z; qr[3] = qv0.w;
        qr[4] = qv1.x; qr[5] = qv1.y; qr[6] = qv1.z; qr[7] = qv1.w;
    }

    // scores: group g handles neighbor jb*4+g; 8 dims per lane via one uint4
    #pragma unroll 4
    for (int jb = 0; jb < 19; jb++) {
        int j = jb * 4 + grp;
        float partial = 0.f;
        bool valid = (j < NBR_) && (gl < 6);
        if (valid) {
            uint4 kv = *(const uint4*)(g_kvh + (size_t)pk[j] * 1536 + head * DH_ + gl * 8);
            float2 f0 = __half22float2(*(__half2*)&kv.x);
            float2 f1 = __half22float2(*(__half2*)&kv.y);
            float2 f2 = __half22float2(*(__half2*)&kv.z);
            float2 f3 = __half22float2(*(__half2*)&kv.w);
            partial = qr[0] * f0.x + qr[1] * f0.y + qr[2] * f1.x + qr[3] * f1.y
                    + qr[4] * f2.x + qr[5] * f2.y + qr[6] * f3.x + qr[7] * f3.y;
        }
        partial += __shfl_xor_sync(0xffffffffu, partial, 1);
        partial += __shfl_xor_sync(0xffffffffu, partial, 2);
        partial += __shfl_xor_sync(0xffffffffu, partial, 4);
        if (gl == 0 && j < NBR_) sc[j] = partial;
    }
    __syncwarp();

    float m = -1e30f;
    for (int j = lane; j < NBR_; j += 32) m = fmaxf(m, sc[j]);
    #pragma unroll
    for (int o = 16; o; o >>= 1) m = fmaxf(m, __shfl_xor_sync(0xffffffffu, m, o));
    float sum = 0.f;
    for (int j = lane; j < NBR_; j += 32) {
        float e = __expf(sc[j] - m);
        sc[j] = e; sum += e;
    }
    #pragma unroll
    for (int o = 16; o; o >>= 1) sum += __shfl_xor_sync(0xffffffffu, sum, o);
    float rs = 1.f / sum;
    for (int j = lane; j < NBR_; j += 32) sc[j] *= rs;
    __syncwarp();

    float acc_a = 0.f, acc_b = 0.f;
    if (lane < 24) {
        #pragma unroll 5
        for (int j = 0; j < NBR_; j++) {
            __half2 vv = *(const __half2*)(g_kvh + (size_t)pk[j] * 1536 + 768 + head * DH_ + 2 * lane);
            float2 vf = __half22float2(vv);
            float pj = sc[j];
            acc_a += pj * vf.x;
            acc_b += pj * vf.y;
        }
        *(__half2*)(g_afin + (size_t)p * KFIN_ + head * DH_ + 2 * lane) =
            __floats2half2_rn(acc_a, acc_b);
    }
}

// ===================== launch =====================
extern "C" void kernel_launch(void* const* d_in, const int* in_sizes, int n_in,
                              void* d_out, int out_size) {
    const float* x       = (const float*)d_in[0];
    const float* emb     = (const float*)d_in[1];
    const float* w_mod   = (const float*)d_in[2];
    const float* b_mod   = (const float*)d_in[3];
    const float* qn_w    = (const float*)d_in[4];
    const float* qn_b    = (const float*)d_in[5];
    const float* kn_w    = (const float*)d_in[6];
    const float* kn_b    = (const float*)d_in[7];
    const float* W_fused = (const float*)d_in[8];
    const float* b_fused = (const float*)d_in[9];
    const float* W_out   = (const float*)d_in[10];
    const float* W_mlp   = (const float*)d_in[11];
    const float* b_mlp   = (const float*)d_in[12];
    float* out = (float*)d_out;

    __half* WF;    cudaGetSymbolAddress((void**)&WF, g_WF);
    __half* WFin;  cudaGetSymbolAddress((void**)&WFin, g_WFin);
    __half* gh;    cudaGetSymbolAddress((void**)&gh, g_h);
    float* gfused; cudaGetSymbolAddress((void**)&gfused, g_fused);
    __half* gkvh;  cudaGetSymbolAddress((void**)&gkvh, g_kvh);
    __half* gafin; cudaGetSymbolAddress((void**)&gafin, g_afin);
    float* gstats; cudaGetSymbolAddress((void**)&gstats, g_stats);

    const int smem1 = 2 * (128 * ROWH + 32 * ROWB) * 2;
    const int smem2 = (2 * (64 * ROWH + 32 * ROWB) * 2 > 128 * 65 * 4)
                        ? 2 * (64 * ROWH + 32 * ROWB) * 2 : 128 * 65 * 4;

    cudaMemsetAsync(gstats, 0, 2 * THW_ * sizeof(float));
    k_cvtWF<<<(DIM_ * FUSEDN_ / 8 + 255) / 256, 256>>>(W_fused);
    k_cvtWFin<<<(KFIN_ * DIM_ / 8 + 255) / 256, 256>>>(W_out, W_mlp);
    k_mod<<<dim3(6, 3), 256>>>(emb, w_mod, b_mod);
    k_stats<<<dim3(96, 3), HW_>>>(x);
    k_applyT<<<dim3(HW_ / 32, DIM_ / 32, T_), dim3(32, 8)>>>(x);
    // fused GEMM: 1728 x 5376, K=768 (q|k fp32, v half, silu(mlp) half)
    k_gemm<4, 0><<<dim3(FUSEDN_ / 128, 14), 256, smem1>>>(
        gh, DIM_, WF, FUSEDN_, DIM_, b_fused, gfused, gkvh, gafin, nullptr, nullptr);
    k_qk<<<(THW_ * HEADS_) / 8, 256>>>(qn_w, qn_b, kn_w, kn_b);
    k_attn<<<(THW_ * HEADS_) / 8, 256>>>();
    // final GEMM: 1728 x 768, K=3840, epilogue writes out (+bias+skip, transposed)
    k_gemm<2, 1><<<dim3(DIM_ / 128, 27), 256, smem2>>>(
        gafin, KFIN_, WFin, DIM_, KFIN_, b_mlp, nullptr, nullptr, nullptr, out, x);
}